// round 10
// baseline (speedup 1.0000x reference)
#include <cuda_runtime.h>
#include <cuda_fp16.h>
#include <math.h>
#include <stdint.h>

// Problem constants
#define BB   2
#define TT   2048
#define DD   1024
#define HH   16
#define DHH  64
#define FFD  4096
#define ROWS (BB*TT)          // 4096
#define SEG  (ROWS * DD)      // 4194304 elements
#define EPSF 1e-5f

__device__ __align__(256) unsigned char g_scratch[190u * 1024u * 1024u];

// ---------------------------------------------------------------------------
// helpers
// ---------------------------------------------------------------------------
__device__ __forceinline__ uint32_t smem_u32(const void* p) {
    uint32_t a;
    asm("{ .reg .u64 t; cvta.to.shared.u64 t, %1; cvt.u32.u64 %0, t; }" : "=r"(a) : "l"(p));
    return a;
}
__device__ __forceinline__ uint32_t sw128(uint32_t bo) {
    return bo ^ ((bo >> 3) & 0x70);
}
__device__ __forceinline__ void cp_async16(uint32_t smem_dst, const void* gmem_src) {
    asm volatile("cp.async.cg.shared.global [%0], [%1], 16;\n" :: "r"(smem_dst), "l"(gmem_src));
}
__device__ __forceinline__ void cp_async16p(void* smem_dst, const void* gmem_src) {
    uint32_t s = smem_u32(smem_dst);
    asm volatile("cp.async.cg.shared.global [%0], [%1], 16;\n" :: "r"(s), "l"(gmem_src));
}
__device__ __forceinline__ void ldsm4a(uint32_t* r, uint32_t a) {
    asm volatile("ldmatrix.sync.aligned.m8n8.x4.shared.b16 {%0,%1,%2,%3}, [%4];"
        : "=r"(r[0]), "=r"(r[1]), "=r"(r[2]), "=r"(r[3]) : "r"(a));
}
__device__ __forceinline__ void ldsm4(uint32_t* r, const __half* p) {
    ldsm4a(r, smem_u32(p));
}
__device__ __forceinline__ void ldsm4t(uint32_t* r, const __half* p) {
    uint32_t a = smem_u32(p);
    asm volatile("ldmatrix.sync.aligned.m8n8.x4.trans.shared.b16 {%0,%1,%2,%3}, [%4];"
        : "=r"(r[0]), "=r"(r[1]), "=r"(r[2]), "=r"(r[3]) : "r"(a));
}
__device__ __forceinline__ void mma16816(float* c, const uint32_t* a, uint32_t b0, uint32_t b1) {
    asm volatile(
        "mma.sync.aligned.m16n8k16.row.col.f32.f16.f16.f32 "
        "{%0,%1,%2,%3}, {%4,%5,%6,%7}, {%8,%9}, {%0,%1,%2,%3};"
        : "+f"(c[0]), "+f"(c[1]), "+f"(c[2]), "+f"(c[3])
        : "r"(a[0]), "r"(a[1]), "r"(a[2]), "r"(a[3]), "r"(b0), "r"(b1));
}
__device__ __forceinline__ uint32_t h2ex2(uint32_t a) {
    uint32_t d;
    asm("ex2.approx.f16x2 %0, %1;" : "=r"(d) : "r"(a));
    return d;
}

// ---------------------------------------------------------------------------
// weight conversion
// ---------------------------------------------------------------------------
__global__ __launch_bounds__(256) void w2h_attn(
    const float* __restrict__ s0, const float* __restrict__ s1,
    const float* __restrict__ s2, const float* __restrict__ s3,
    __half* __restrict__ dst)
{
    const size_t idx = ((size_t)blockIdx.x * 256 + threadIdx.x) * 4;
    const int seg = (int)(idx >> 20);
    const float* s = (seg == 0) ? s0 : (seg == 1) ? s1 : (seg == 2) ? s2 : s3;
    float4 v = *(const float4*)(s + (idx & 0xFFFFF));
    *(__half2*)(dst + idx)     = __floats2half2_rn(v.x, v.y);
    *(__half2*)(dst + idx + 2) = __floats2half2_rn(v.z, v.w);
}
__global__ __launch_bounds__(256) void w2h_ff(
    const float* __restrict__ s0, const float* __restrict__ s1,
    __half* __restrict__ dst)
{
    const size_t idx = ((size_t)blockIdx.x * 256 + threadIdx.x) * 4;
    const int seg = (int)(idx >> 22);
    const float* s = (seg == 0) ? s0 : s1;
    float4 v = *(const float4*)(s + (idx & 0x3FFFFF));
    *(__half2*)(dst + idx)     = __floats2half2_rn(v.x, v.y);
    *(__half2*)(dst + idx + 2) = __floats2half2_rn(v.z, v.w);
}

// ---------------------------------------------------------------------------
// LayerNorm -> split hi/lo fp16
// ---------------------------------------------------------------------------
__global__ __launch_bounds__(256) void ln_split_kernel(
    const float* __restrict__ x, const float* __restrict__ g,
    const float* __restrict__ b, __half* __restrict__ ohi, __half* __restrict__ olo)
{
    const int row = blockIdx.x;
    const int tid = threadIdx.x;
    const float* xr = x + (size_t)row * DD;

    float4 v = *(const float4*)(xr + tid * 4);
    float s  = v.x + v.y + v.z + v.w;
    float ss = v.x * v.x + v.y * v.y + v.z * v.z + v.w * v.w;

    #pragma unroll
    for (int off = 16; off > 0; off >>= 1) {
        s  += __shfl_xor_sync(0xffffffff, s,  off);
        ss += __shfl_xor_sync(0xffffffff, ss, off);
    }
    __shared__ float sbuf[8], ssbuf[8];
    const int warp = tid >> 5, lane = tid & 31;
    if (lane == 0) { sbuf[warp] = s; ssbuf[warp] = ss; }
    __syncthreads();
    float S = 0.f, SS = 0.f;
    #pragma unroll
    for (int i = 0; i < 8; i++) { S += sbuf[i]; SS += ssbuf[i]; }

    const float mu  = S * (1.0f / DD);
    const float var = SS * (1.0f / DD) - mu * mu;
    const float rs  = rsqrtf(var + EPSF);

    float4 gg = *(const float4*)(g + tid * 4);
    float4 bb = *(const float4*)(b + tid * 4);
    float y0 = (v.x - mu) * rs * gg.x + bb.x;
    float y1 = (v.y - mu) * rs * gg.y + bb.y;
    float y2 = (v.z - mu) * rs * gg.z + bb.z;
    float y3 = (v.w - mu) * rs * gg.w + bb.w;

    __half h0 = __float2half_rn(y0), h1 = __float2half_rn(y1);
    __half h2 = __float2half_rn(y2), h3 = __float2half_rn(y3);
    const size_t base = (size_t)row * DD + tid * 4;
    *(__half2*)(ohi + base)     = __halves2half2(h0, h1);
    *(__half2*)(ohi + base + 2) = __halves2half2(h2, h3);
    *(__half2*)(olo + base)     = __halves2half2(
        __float2half_rn(y0 - __half2float(h0)), __float2half_rn(y1 - __half2float(h1)));
    *(__half2*)(olo + base + 2) = __halves2half2(
        __float2half_rn(y2 - __half2float(h2)), __float2half_rn(y3 - __half2float(h3)));
}

// ---------------------------------------------------------------------------
// fp16 GEMM: C[M,N] = A[M,K] @ W[N,K]^T, A = Ah (+ Al if NLIMB==2 & use_lo)
// 128x128 tile, BK=64 (128B rows, XOR-swizzled), cp.async pipeline:
//   NLIMB==2 -> 2 stages (96KB), NLIMB==1 -> 3 stages (96KB, wait_group 1)
// ONE __syncthreads per k64 iter. 8 warps (2x4), 64x32 per warp.
// EPI: 1 C=acc+R(f32), 2 gelu->Ohi, 3 C+=acc, 5 segmented split (QKV;
//      V-segment blocks bn>=2048 run 1-limb and store hi only)
// ---------------------------------------------------------------------------
#define GM 128
#define GN 128
#define GK 64
#define TILE_B 16384u

template<int EPI, int NLIMB>
__global__ __launch_bounds__(256) void gemm_f16(
    const __half* __restrict__ Ah, const __half* __restrict__ Al,
    const __half* __restrict__ Wh, float* __restrict__ C,
    const float* __restrict__ R, __half* __restrict__ Ohi, __half* __restrict__ Olo,
    int M, int N, int K)
{
    extern __shared__ unsigned char smraw[];
    const uint32_t smb = smem_u32(smraw);

    constexpr int PL = NLIMB + 1;                 // planes per stage (A limbs + W)
    constexpr uint32_t STAGEB = PL * TILE_B;
    constexpr int NSTAGE = (NLIMB == 1) ? 3 : 2;

    const int tid   = threadIdx.x;
    const int lane  = tid & 31;
    const int warp  = tid >> 5;
    const int wm    = (warp >> 2) * 64;
    const int wn    = (warp & 3) * 32;
    const int group = lane >> 2;
    const int t4    = lane & 3;

    const int bm = blockIdx.y * GM;
    const int bn = blockIdx.x * GN;

    // V segment of fused QKV never consumes the lo limb
    const bool use_lo = (NLIMB == 2) && (EPI != 5 || bn < 2 * DD);

    const int a_row = (lane & 7) + ((lane >> 3) & 1) * 8;
    const int a_k   = (lane >> 4) * 8;
    const int b_row = (lane & 7) + ((lane >> 4) & 1) * 8;
    const int b_k   = ((lane >> 3) & 1) * 8;

    float c[4][4][4];
    #pragma unroll
    for (int mi = 0; mi < 4; mi++)
        #pragma unroll
        for (int ni = 0; ni < 4; ni++)
            #pragma unroll
            for (int f = 0; f < 4; f++) c[mi][ni][f] = 0.f;

    const int KT = K / GK;

    #define STAGE_LOAD(st, k0)                                                      \
    {                                                                               \
        const uint32_t sb_ = smb + (st) * STAGEB;                                   \
        _Pragma("unroll")                                                           \
        for (int i = 0; i < 4 * PL; i++) {                                          \
            const int pl  = i >> 2;                                                 \
            if (pl == 1 && NLIMB == 2 && !use_lo) continue;                         \
            const int id  = (i & 3) * 256 + tid;                                    \
            const int row = id >> 3;                                                \
            const int kq  = id & 7;                                                 \
            const uint32_t bo = row * 128 + kq * 16;                                \
            const __half* src; size_t gr;                                           \
            if (pl == NLIMB)      { src = Wh; gr = (size_t)(bn + row) * K; }        \
            else if (pl == 0)     { src = Ah; gr = (size_t)(bm + row) * K; }        \
            else                  { src = Al; gr = (size_t)(bm + row) * K; }        \
            cp_async16(sb_ + pl * TILE_B + sw128(bo), src + gr + (k0) + kq * 8);    \
        }                                                                           \
        asm volatile("cp.async.commit_group;\n");                                   \
    }

    STAGE_LOAD(0, 0)
    if (NSTAGE == 3 && KT > 1) STAGE_LOAD(1, GK)

    for (int kt = 0; kt < KT; kt++) {
        if (NSTAGE == 3 && kt < KT - 1) {
            asm volatile("cp.async.wait_group 1;\n");
        } else {
            asm volatile("cp.async.wait_group 0;\n");
        }
        __syncthreads();                       // data visible + oldest stage free
        if (kt + NSTAGE - 1 < KT) STAGE_LOAD((kt + NSTAGE - 1) % NSTAGE, (kt + NSTAGE - 1) * GK)

        const uint32_t sb = smb + (kt % NSTAGE) * STAGEB;
        #pragma unroll
        for (int ks = 0; ks < 4; ks++) {
            uint32_t bf[4][2];
            #pragma unroll
            for (int ng = 0; ng < 2; ng++) {
                uint32_t r[4];
                ldsm4a(r, sb + NLIMB * TILE_B +
                       sw128((wn + ng * 16 + b_row) * 128 + (ks * 16 + b_k) * 2));
                bf[2 * ng + 0][0] = r[0]; bf[2 * ng + 0][1] = r[1];
                bf[2 * ng + 1][0] = r[2]; bf[2 * ng + 1][1] = r[3];
            }
            #pragma unroll
            for (int mi = 0; mi < 4; mi++) {
                uint32_t ah[4];
                const uint32_t bo = (wm + mi * 16 + a_row) * 128 + (ks * 16 + a_k) * 2;
                ldsm4a(ah, sb + sw128(bo));
                if (NLIMB == 2) {
                    if (use_lo) {
                        uint32_t al[4];
                        ldsm4a(al, sb + TILE_B + sw128(bo));
                        #pragma unroll
                        for (int ni = 0; ni < 4; ni++) {
                            mma16816(c[mi][ni], ah, bf[ni][0], bf[ni][1]);
                            mma16816(c[mi][ni], al, bf[ni][0], bf[ni][1]);
                        }
                    } else {
                        #pragma unroll
                        for (int ni = 0; ni < 4; ni++)
                            mma16816(c[mi][ni], ah, bf[ni][0], bf[ni][1]);
                    }
                } else {
                    #pragma unroll
                    for (int ni = 0; ni < 4; ni++)
                        mma16816(c[mi][ni], ah, bf[ni][0], bf[ni][1]);
                }
            }
        }
    }

    // epilogue
    #pragma unroll
    for (int mi = 0; mi < 4; mi++) {
        #pragma unroll
        for (int hf = 0; hf < 2; hf++) {
            const int row = bm + wm + mi * 16 + group + hf * 8;
            #pragma unroll
            for (int ni = 0; ni < 4; ni++) {
                const int col = bn + wn + ni * 8 + t4 * 2;
                float v0 = c[mi][ni][hf * 2 + 0];
                float v1 = c[mi][ni][hf * 2 + 1];
                if (EPI == 1) {
                    float2 rr = *(const float2*)(R + (size_t)row * N + col);
                    float2 o; o.x = v0 + rr.x; o.y = v1 + rr.y;
                    *(float2*)(C + (size_t)row * N + col) = o;
                } else if (EPI == 2) {
                    v0 = 0.5f * v0 * (1.0f + erff(v0 * 0.70710678118654752f));
                    v1 = 0.5f * v1 * (1.0f + erff(v1 * 0.70710678118654752f));
                    *(__half2*)(Ohi + (size_t)row * N + col) =
                        __floats2half2_rn(v0, v1);
                } else if (EPI == 5) {
                    const int seg = col >> 10;
                    const int lc  = col & 1023;
                    const size_t di = ((size_t)seg * ROWS + row) * DD + lc;
                    __half h0 = __float2half_rn(v0), h1 = __float2half_rn(v1);
                    *(__half2*)(Ohi + di) = __halves2half2(h0, h1);
                    if (seg < 2) {   // V consumer never reads lo
                        *(__half2*)(Olo + di) = __halves2half2(
                            __float2half_rn(v0 - __half2float(h0)),
                            __float2half_rn(v1 - __half2float(h1)));
                    }
                } else {  // EPI == 3
                    float2 cc = *(const float2*)(C + (size_t)row * N + col);
                    float2 o; o.x = v0 + cc.x; o.y = v1 + cc.y;
                    *(float2*)(C + (size_t)row * N + col) = o;
                }
            }
        }
    }
}

// ---------------------------------------------------------------------------
// Tensor-core causal flash attention.
// 256 thr, 8 warps x 16 q-rows; 64-key tiles (Kh,Kl,Vh) double-buffered;
// S = QhKh + QlKh + QhKl; P@Vh; row-sum l via ones-MMA. Output: hi fp16.
// ---------------------------------------------------------------------------
#define ATS 72
#define QBUF (128 * ATS)
#define KVT  (64 * ATS)
#define KVSTG3 (3 * KVT)
#define ASMEM ((2u * KVSTG3 + 2u * QBUF) * sizeof(__half))   // 92160 B

__global__ __launch_bounds__(256) void attn_tc(
    const __half* __restrict__ Qh, const __half* __restrict__ Ql,
    const __half* __restrict__ Kh, const __half* __restrict__ Kl,
    const __half* __restrict__ Vh,
    __half* __restrict__ Ohi)
{
    extern __shared__ __half sm[];
    __half* sKV = sm;                  // [2][KVSTG3]
    __half* sQh = sm + 2 * KVSTG3;
    __half* sQl = sQh + QBUF;

    const int tid  = threadIdx.x;
    const int lane = tid & 31;
    const int warp = tid >> 5;
    const int wrow = warp * 16;
    const int group = lane >> 2;
    const int t4    = lane & 3;

    const int qtile = gridDim.x - 1 - blockIdx.x;   // long blocks first
    const int bh = blockIdx.y;
    const int b = bh >> 4, h = bh & 15;
    const int qbase = qtile * 128;
    const int hoff  = h * DHH;
    const size_t tokb = (size_t)b * TT;

    const int a_row = (lane & 7) + ((lane >> 3) & 1) * 8;
    const int a_k   = (lane >> 4) * 8;
    const int b_row = (lane & 7) + ((lane >> 4) & 1) * 8;
    const int b_k   = ((lane >> 3) & 1) * 8;
    const int v_row = (lane & 7) + ((lane >> 3) & 1) * 8;
    const int v_col = (lane >> 4) * 8;

    // group 0: Q (hi + lo)
    #pragma unroll
    for (int i = 0; i < 8; i++) {
        const int buf = i >> 2;
        const int within = (i & 3) * 256 + tid;
        const int row = within >> 3;
        const int c8  = (within & 7) * 8;
        const __half* src = (buf == 0 ? Qh : Ql) + (tokb + qbase + row) * DD + hoff + c8;
        cp_async16p((buf == 0 ? sQh : sQl) + row * ATS + c8, src);
    }
    asm volatile("cp.async.commit_group;\n");

    #define KV_LOAD(st, key0)                                                        \
    {                                                                                \
        _Pragma("unroll")                                                            \
        for (int i = 0; i < 6; i++) {                                                \
            const int tile = i >> 1;                                                 \
            const int row  = (i & 1) * 32 + (tid >> 3);                              \
            const int c8   = (tid & 7) * 8;                                          \
            const __half* src = (tile == 0 ? Kh : tile == 1 ? Kl : Vh)               \
                                + (tokb + (key0) + row) * DD + hoff + c8;            \
            cp_async16p(&sKV[(st) * KVSTG3 + tile * KVT + row * ATS + c8], src);     \
        }                                                                            \
        asm volatile("cp.async.commit_group;\n");                                    \
    }

    KV_LOAD(0, 0)                                // group 1
    asm volatile("cp.async.wait_group 1;\n");    // Q done
    __syncthreads();

    uint32_t qfh[4][4], qfl[4][4];
    #pragma unroll
    for (int kc = 0; kc < 4; kc++) {
        const int off = (wrow + a_row) * ATS + kc * 16 + a_k;
        ldsm4(qfh[kc], &sQh[off]);
        ldsm4(qfl[kc], &sQl[off]);
    }

    float o[8][4];
    #pragma unroll
    for (int ni = 0; ni < 8; ni++)
        #pragma unroll
        for (int f = 0; f < 4; f++) o[ni][f] = 0.f;
    float m0 = -INFINITY, m1 = -INFINITY, l0 = 0.f, l1 = 0.f;

    const float SC2 = 0.125f * 1.4426950408889634f;
    const uint32_t ONES2 = 0x3C003C00u;          // half2(1.0, 1.0)
    const int nkt = 2 * qtile + 2;

    for (int kt = 0; kt < nkt; kt++) {
        const int st = kt & 1;
        asm volatile("cp.async.wait_group 0;\n");   // kv(kt) done
        __syncthreads();
        if (kt + 1 < nkt) KV_LOAD(st ^ 1, (kt + 1) * 64)

        const __half* pKh = &sKV[st * KVSTG3 + 0 * KVT];
        const __half* pKl = &sKV[st * KVSTG3 + 1 * KVT];
        const __half* pVh = &sKV[st * KVSTG3 + 2 * KVT];

        float s[8][4];
        #pragma unroll
        for (int ni = 0; ni < 8; ni++)
            #pragma unroll
            for (int f = 0; f < 4; f++) s[ni][f] = 0.f;

        #pragma unroll
        for (int kc = 0; kc < 4; kc++) {
            #pragma unroll
            for (int ntp = 0; ntp < 4; ntp++) {
                uint32_t rh[4], rl[4];
                const int off = (ntp * 16 + b_row) * ATS + kc * 16 + b_k;
                ldsm4(rh, pKh + off);
                ldsm4(rl, pKl + off);
                mma16816(s[2*ntp+0], qfh[kc], rh[0], rh[1]);
                mma16816(s[2*ntp+1], qfh[kc], rh[2], rh[3]);
                mma16816(s[2*ntp+0], qfl[kc], rh[0], rh[1]);
                mma16816(s[2*ntp+1], qfl[kc], rh[2], rh[3]);
                mma16816(s[2*ntp+0], qfh[kc], rl[0], rl[1]);
                mma16816(s[2*ntp+1], qfh[kc], rl[2], rl[3]);
            }
        }

        const int r0 = qbase + wrow + group;
        const int r1 = r0 + 8;
        const bool needmask = (kt * 64 + 63) > (qbase + wrow);
        #pragma unroll
        for (int ni = 0; ni < 8; ni++) {
            #pragma unroll
            for (int f = 0; f < 4; f++) s[ni][f] *= SC2;
            if (needmask) {
                const int col = kt * 64 + ni * 8 + t4 * 2;
                if (col > r0)     s[ni][0] = -1e30f;
                if (col + 1 > r0) s[ni][1] = -1e30f;
                if (col > r1)     s[ni][2] = -1e30f;
                if (col + 1 > r1) s[ni][3] = -1e30f;
            }
        }

        float rm0 = -INFINITY, rm1 = -INFINITY;
        #pragma unroll
        for (int ni = 0; ni < 8; ni++) {
            rm0 = fmaxf(rm0, fmaxf(s[ni][0], s[ni][1]));
            rm1 = fmaxf(rm1, fmaxf(s[ni][2], s[ni][3]));
        }
        rm0 = fmaxf(rm0, __shfl_xor_sync(0xffffffff, rm0, 1));
        rm0 = fmaxf(rm0, __shfl_xor_sync(0xffffffff, rm0, 2));
        rm1 = fmaxf(rm1, __shfl_xor_sync(0xffffffff, rm1, 1));
        rm1 = fmaxf(rm1, __shfl_xor_sync(0xffffffff, rm1, 2));

        const float nm0 = fmaxf(m0, rm0), nm1 = fmaxf(m1, rm1);
        const float al0 = exp2f(m0 - nm0), al1 = exp2f(m1 - nm1);
        l0 *= al0; l1 *= al1;
        m0 = nm0; m1 = nm1;
        #pragma unroll
        for (int ni = 0; ni < 8; ni++) {
            o[ni][0] *= al0; o[ni][1] *= al0;
            o[ni][2] *= al1; o[ni][3] *= al1;
        }

        // p = exp2(s - m), kept in fp16x2 fragments (masked -> -inf -> 0)
        uint32_t pf[8][2];
        #pragma unroll
        for (int ni = 0; ni < 8; ni++) {
            __half2 t0 = __floats2half2_rn(s[ni][0] - m0, s[ni][1] - m0);
            __half2 t1 = __floats2half2_rn(s[ni][2] - m1, s[ni][3] - m1);
            pf[ni][0] = h2ex2(*(uint32_t*)&t0);
            pf[ni][1] = h2ex2(*(uint32_t*)&t1);
        }

        // O += P @ Vh; l += P @ ones (row sums via MMA, no shuffles)
        float lacc[4] = {0.f, 0.f, 0.f, 0.f};
        #pragma unroll
        for (int kc = 0; kc < 4; kc++) {
            uint32_t a[4] = { pf[2*kc][0], pf[2*kc][1], pf[2*kc+1][0], pf[2*kc+1][1] };
            mma16816(lacc, a, ONES2, ONES2);
            #pragma unroll
            for (int ntp = 0; ntp < 4; ntp++) {
                uint32_t rh[4];
                const int off = (kc * 16 + v_row) * ATS + ntp * 16 + v_col;
                ldsm4t(rh, pVh + off);
                mma16816(o[2*ntp+0], a, rh[0], rh[1]);
                mma16816(o[2*ntp+1], a, rh[2], rh[3]);
            }
        }
        l0 += lacc[0];
        l1 += lacc[2];
    }

    const float il0 = 1.0f / l0, il1 = 1.0f / l1;
    const size_t gr0 = (tokb + qbase + wrow + group) * DD + hoff;
    const size_t gr1 = gr0 + 8 * DD;
    #pragma unroll
    for (int ni = 0; ni < 8; ni++) {
        const int col = ni * 8 + t4 * 2;
        *(__half2*)(Ohi + gr0 + col) = __floats2half2_rn(o[ni][0] * il0, o[ni][1] * il0);
        *(__half2*)(Ohi + gr1 + col) = __floats2half2_rn(o[ni][2] * il1, o[ni][3] * il1);
    }
}

// ---------------------------------------------------------------------------
// kernel_launch
// ---------------------------------------------------------------------------
extern "C" void kernel_launch(void* const* d_in, const int* in_sizes, int n_in,
                              void* d_out, int out_size)
{
    const float* x     = (const float*)d_in[0];
    const float* ln1_g = (const float*)d_in[2];
    const float* ln1_b = (const float*)d_in[3];
    const float* ln2_g = (const float*)d_in[4];
    const float* ln2_b = (const float*)d_in[5];
    const float* Wq    = (const float*)d_in[6];
    const float* Wk    = (const float*)d_in[7];
    const float* Wv    = (const float*)d_in[8];
    const float* Wo    = (const float*)d_in[9];
    const float* Wff1  = (const float*)d_in[10];
    const float* Wff2  = (const float*)d_in[11];
    float* out = (float*)d_out;

    unsigned char* base = nullptr;
    cudaGetSymbolAddress((void**)&base, g_scratch);
    size_t off = 0;
    auto carve = [&](size_t bytes) { void* p = base + off; off += bytes; return p; };

    __half* qkv_hi = (__half*)carve((size_t)3 * SEG * 2);
    __half* qkv_lo = (__half*)carve((size_t)3 * SEG * 2);   // V segment unused
    __half* h_hi   = (__half*)carve((size_t)SEG * 2);
    __half* h_lo   = (__half*)carve((size_t)SEG * 2);
    __half* att_hi = (__half*)carve((size_t)SEG * 2);
    __half* ff_hi  = (__half*)carve((size_t)ROWS * FFD * 2);
    __half* Wqkv_h = (__half*)carve((size_t)3 * DD * DD * 2);
    __half* Wo_h   = (__half*)carve((size_t)DD * DD * 2);
    __half* Wff_h  = (__half*)carve((size_t)2 * FFD * DD * 2);

    __half* Wf1_h = Wff_h;
    __half* Wf2_h = Wff_h + (size_t)FFD * DD;

    const uint32_t SM2 = 2u * 3u * TILE_B;   // NLIMB=2: 2 stages x 48KB = 98304 B
    const uint32_t SM1 = 3u * 2u * TILE_B;   // NLIMB=1: 3 stages x 32KB = 98304 B
    cudaFuncSetAttribute((const void*)gemm_f16<5,2>, cudaFuncAttributeMaxDynamicSharedMemorySize, (int)SM2);
    cudaFuncSetAttribute((const void*)gemm_f16<1,1>, cudaFuncAttributeMaxDynamicSharedMemorySize, (int)SM1);
    cudaFuncSetAttribute((const void*)gemm_f16<2,1>, cudaFuncAttributeMaxDynamicSharedMemorySize, (int)SM1);
    cudaFuncSetAttribute((const void*)gemm_f16<3,1>, cudaFuncAttributeMaxDynamicSharedMemorySize, (int)SM1);
    cudaFuncSetAttribute((const void*)attn_tc, cudaFuncAttributeMaxDynamicSharedMemorySize, (int)ASMEM);

    // launches ordered so ncu -s 5 captures launch #6 = Wo GEMM
    w2h_attn<<<4 * DD * DD / 1024, 256>>>(Wq, Wk, Wv, Wo, Wqkv_h);
    w2h_ff<<<2 * FFD * DD / 1024, 256>>>(Wff1, Wff2, Wff_h);

    ln_split_kernel<<<ROWS, 256>>>(x, ln1_g, ln1_b, h_hi, h_lo);

    // fused QKV: N = 3072, split A on Q/K blocks only
    gemm_f16<5,2><<<dim3(3 * DD / GN, ROWS / GM), 256, SM2>>>(
        h_hi, h_lo, Wqkv_h, nullptr, nullptr, qkv_hi, qkv_lo, ROWS, 3 * DD, DD);

    attn_tc<<<dim3(TT / 128, BB * HH), 256, ASMEM>>>(
        qkv_hi, qkv_lo, qkv_hi + SEG, qkv_lo + SEG, qkv_hi + 2 * SEG, att_hi);

    gemm_f16<1,1><<<dim3(DD / GN, ROWS / GM), 256, SM1>>>(
        att_hi, nullptr, Wo_h, out, x, nullptr, nullptr, ROWS, DD, DD);

    ln_split_kernel<<<ROWS, 256>>>(out, ln2_g, ln2_b, h_hi, h_lo);

    gemm_f16<2,1><<<dim3(FFD / GN, ROWS / GM), 256, SM1>>>(
        h_hi, nullptr, Wf1_h, nullptr, nullptr, ff_hi, nullptr, ROWS, FFD, DD);

    gemm_f16<3,1><<<dim3(DD / GN, ROWS / GM), 256, SM1>>>(
        ff_hi, nullptr, Wf2_h, out, nullptr, nullptr, nullptr, ROWS, DD, FFD);
}

// round 11
// speedup vs baseline: 1.0857x; 1.0857x over previous
#include <cuda_runtime.h>
#include <cuda_fp16.h>
#include <math.h>
#include <stdint.h>

// Problem constants
#define BB   2
#define TT   2048
#define DD   1024
#define HH   16
#define DHH  64
#define FFD  4096
#define ROWS (BB*TT)          // 4096
#define SEG  (ROWS * DD)      // 4194304 elements
#define EPSF 1e-5f

__device__ __align__(256) unsigned char g_scratch[190u * 1024u * 1024u];

// ---------------------------------------------------------------------------
// helpers
// ---------------------------------------------------------------------------
__device__ __forceinline__ uint32_t smem_u32(const void* p) {
    uint32_t a;
    asm("{ .reg .u64 t; cvta.to.shared.u64 t, %1; cvt.u32.u64 %0, t; }" : "=r"(a) : "l"(p));
    return a;
}
__device__ __forceinline__ uint32_t sw128(uint32_t bo) {
    return bo ^ ((bo >> 3) & 0x70);
}
__device__ __forceinline__ void cp_async16(uint32_t smem_dst, const void* gmem_src) {
    asm volatile("cp.async.cg.shared.global [%0], [%1], 16;\n" :: "r"(smem_dst), "l"(gmem_src));
}
__device__ __forceinline__ void cp_async16p(void* smem_dst, const void* gmem_src) {
    uint32_t s = smem_u32(smem_dst);
    asm volatile("cp.async.cg.shared.global [%0], [%1], 16;\n" :: "r"(s), "l"(gmem_src));
}
__device__ __forceinline__ void ldsm4a(uint32_t* r, uint32_t a) {
    asm volatile("ldmatrix.sync.aligned.m8n8.x4.shared.b16 {%0,%1,%2,%3}, [%4];"
        : "=r"(r[0]), "=r"(r[1]), "=r"(r[2]), "=r"(r[3]) : "r"(a));
}
__device__ __forceinline__ void ldsm4(uint32_t* r, const __half* p) {
    ldsm4a(r, smem_u32(p));
}
__device__ __forceinline__ void ldsm4t(uint32_t* r, const __half* p) {
    uint32_t a = smem_u32(p);
    asm volatile("ldmatrix.sync.aligned.m8n8.x4.trans.shared.b16 {%0,%1,%2,%3}, [%4];"
        : "=r"(r[0]), "=r"(r[1]), "=r"(r[2]), "=r"(r[3]) : "r"(a));
}
__device__ __forceinline__ void mma16816(float* c, const uint32_t* a, uint32_t b0, uint32_t b1) {
    asm volatile(
        "mma.sync.aligned.m16n8k16.row.col.f32.f16.f16.f32 "
        "{%0,%1,%2,%3}, {%4,%5,%6,%7}, {%8,%9}, {%0,%1,%2,%3};"
        : "+f"(c[0]), "+f"(c[1]), "+f"(c[2]), "+f"(c[3])
        : "r"(a[0]), "r"(a[1]), "r"(a[2]), "r"(a[3]), "r"(b0), "r"(b1));
}
__device__ __forceinline__ uint32_t h2ex2(uint32_t a) {
    uint32_t d;
    asm("ex2.approx.f16x2 %0, %1;" : "=r"(d) : "r"(a));
    return d;
}

// ---------------------------------------------------------------------------
// weight conversion
// ---------------------------------------------------------------------------
__global__ __launch_bounds__(256) void w2h_attn(
    const float* __restrict__ s0, const float* __restrict__ s1,
    const float* __restrict__ s2, const float* __restrict__ s3,
    __half* __restrict__ dst)
{
    const size_t idx = ((size_t)blockIdx.x * 256 + threadIdx.x) * 4;
    const int seg = (int)(idx >> 20);
    const float* s = (seg == 0) ? s0 : (seg == 1) ? s1 : (seg == 2) ? s2 : s3;
    float4 v = *(const float4*)(s + (idx & 0xFFFFF));
    *(__half2*)(dst + idx)     = __floats2half2_rn(v.x, v.y);
    *(__half2*)(dst + idx + 2) = __floats2half2_rn(v.z, v.w);
}
__global__ __launch_bounds__(256) void w2h_ff(
    const float* __restrict__ s0, const float* __restrict__ s1,
    __half* __restrict__ dst)
{
    const size_t idx = ((size_t)blockIdx.x * 256 + threadIdx.x) * 4;
    const int seg = (int)(idx >> 22);
    const float* s = (seg == 0) ? s0 : s1;
    float4 v = *(const float4*)(s + (idx & 0x3FFFFF));
    *(__half2*)(dst + idx)     = __floats2half2_rn(v.x, v.y);
    *(__half2*)(dst + idx + 2) = __floats2half2_rn(v.z, v.w);
}

// ---------------------------------------------------------------------------
// LayerNorm -> split hi/lo fp16
// ---------------------------------------------------------------------------
__global__ __launch_bounds__(256) void ln_split_kernel(
    const float* __restrict__ x, const float* __restrict__ g,
    const float* __restrict__ b, __half* __restrict__ ohi, __half* __restrict__ olo)
{
    const int row = blockIdx.x;
    const int tid = threadIdx.x;
    const float* xr = x + (size_t)row * DD;

    float4 v = *(const float4*)(xr + tid * 4);
    float s  = v.x + v.y + v.z + v.w;
    float ss = v.x * v.x + v.y * v.y + v.z * v.z + v.w * v.w;

    #pragma unroll
    for (int off = 16; off > 0; off >>= 1) {
        s  += __shfl_xor_sync(0xffffffff, s,  off);
        ss += __shfl_xor_sync(0xffffffff, ss, off);
    }
    __shared__ float sbuf[8], ssbuf[8];
    const int warp = tid >> 5, lane = tid & 31;
    if (lane == 0) { sbuf[warp] = s; ssbuf[warp] = ss; }
    __syncthreads();
    float S = 0.f, SS = 0.f;
    #pragma unroll
    for (int i = 0; i < 8; i++) { S += sbuf[i]; SS += ssbuf[i]; }

    const float mu  = S * (1.0f / DD);
    const float var = SS * (1.0f / DD) - mu * mu;
    const float rs  = rsqrtf(var + EPSF);

    float4 gg = *(const float4*)(g + tid * 4);
    float4 bb = *(const float4*)(b + tid * 4);
    float y0 = (v.x - mu) * rs * gg.x + bb.x;
    float y1 = (v.y - mu) * rs * gg.y + bb.y;
    float y2 = (v.z - mu) * rs * gg.z + bb.z;
    float y3 = (v.w - mu) * rs * gg.w + bb.w;

    __half h0 = __float2half_rn(y0), h1 = __float2half_rn(y1);
    __half h2 = __float2half_rn(y2), h3 = __float2half_rn(y3);
    const size_t base = (size_t)row * DD + tid * 4;
    *(__half2*)(ohi + base)     = __halves2half2(h0, h1);
    *(__half2*)(ohi + base + 2) = __halves2half2(h2, h3);
    *(__half2*)(olo + base)     = __halves2half2(
        __float2half_rn(y0 - __half2float(h0)), __float2half_rn(y1 - __half2float(h1)));
    *(__half2*)(olo + base + 2) = __halves2half2(
        __float2half_rn(y2 - __half2float(h2)), __float2half_rn(y3 - __half2float(h3)));
}

// ---------------------------------------------------------------------------
// fp16 GEMM: C[M,N] = A[M,K] @ W[N,K]^T, A = Ah (+ Al if NLIMB==2 & use_lo)
// 128x128 tile, BK=64 (128B rows, XOR-swizzled), 2-stage cp.async,
// ONE __syncthreads per k64 iter. 8 warps (2x4), 64x32 per warp.
// NLIMB==1: stage 32KB -> 64KB total -> 3 CTAs/SM.
// EPI: 1 C=acc+R(f32), 2 gelu->Ohi, 3 C+=acc, 5 segmented split (QKV;
//      V-segment blocks bn>=2048 run 1-limb and store hi only)
// ---------------------------------------------------------------------------
#define GM 128
#define GN 128
#define GK 64
#define TILE_B 16384u

template<int EPI, int NLIMB>
__global__ __launch_bounds__(256) void gemm_f16(
    const __half* __restrict__ Ah, const __half* __restrict__ Al,
    const __half* __restrict__ Wh, float* __restrict__ C,
    const float* __restrict__ R, __half* __restrict__ Ohi, __half* __restrict__ Olo,
    int M, int N, int K)
{
    extern __shared__ unsigned char smraw[];
    const uint32_t smb = smem_u32(smraw);

    constexpr int PL = NLIMB + 1;                 // planes per stage (A limbs + W)
    constexpr uint32_t STAGEB = PL * TILE_B;

    const int tid   = threadIdx.x;
    const int lane  = tid & 31;
    const int warp  = tid >> 5;
    const int wm    = (warp >> 2) * 64;
    const int wn    = (warp & 3) * 32;
    const int group = lane >> 2;
    const int t4    = lane & 3;

    const int bm = blockIdx.y * GM;
    const int bn = blockIdx.x * GN;

    // V segment of fused QKV never consumes the lo limb
    const bool use_lo = (NLIMB == 2) && (EPI != 5 || bn < 2 * DD);

    const int a_row = (lane & 7) + ((lane >> 3) & 1) * 8;
    const int a_k   = (lane >> 4) * 8;
    const int b_row = (lane & 7) + ((lane >> 4) & 1) * 8;
    const int b_k   = ((lane >> 3) & 1) * 8;

    float c[4][4][4];
    #pragma unroll
    for (int mi = 0; mi < 4; mi++)
        #pragma unroll
        for (int ni = 0; ni < 4; ni++)
            #pragma unroll
            for (int f = 0; f < 4; f++) c[mi][ni][f] = 0.f;

    const int KT = K / GK;

    #define STAGE_LOAD(st, k0)                                                      \
    {                                                                               \
        const uint32_t sb_ = smb + (st) * STAGEB;                                   \
        _Pragma("unroll")                                                           \
        for (int i = 0; i < 4 * PL; i++) {                                          \
            const int pl  = i >> 2;                                                 \
            if (pl == 1 && NLIMB == 2 && !use_lo) continue;                         \
            const int id  = (i & 3) * 256 + tid;                                    \
            const int row = id >> 3;                                                \
            const int kq  = id & 7;                                                 \
            const uint32_t bo = row * 128 + kq * 16;                                \
            const __half* src; size_t gr;                                           \
            if (pl == NLIMB)      { src = Wh; gr = (size_t)(bn + row) * K; }        \
            else if (pl == 0)     { src = Ah; gr = (size_t)(bm + row) * K; }        \
            else                  { src = Al; gr = (size_t)(bm + row) * K; }        \
            cp_async16(sb_ + pl * TILE_B + sw128(bo), src + gr + (k0) + kq * 8);    \
        }                                                                           \
        asm volatile("cp.async.commit_group;\n");                                   \
    }

    STAGE_LOAD(0, 0)

    for (int kt = 0; kt < KT; kt++) {
        asm volatile("cp.async.wait_group 0;\n");
        __syncthreads();                       // data visible + prev stage free
        if (kt + 1 < KT) STAGE_LOAD((kt + 1) & 1, (kt + 1) * GK)

        const uint32_t sb = smb + (kt & 1) * STAGEB;
        #pragma unroll
        for (int ks = 0; ks < 4; ks++) {
            uint32_t bf[4][2];
            #pragma unroll
            for (int ng = 0; ng < 2; ng++) {
                uint32_t r[4];
                ldsm4a(r, sb + NLIMB * TILE_B +
                       sw128((wn + ng * 16 + b_row) * 128 + (ks * 16 + b_k) * 2));
                bf[2 * ng + 0][0] = r[0]; bf[2 * ng + 0][1] = r[1];
                bf[2 * ng + 1][0] = r[2]; bf[2 * ng + 1][1] = r[3];
            }
            #pragma unroll
            for (int mi = 0; mi < 4; mi++) {
                uint32_t ah[4];
                const uint32_t bo = (wm + mi * 16 + a_row) * 128 + (ks * 16 + a_k) * 2;
                ldsm4a(ah, sb + sw128(bo));
                if (NLIMB == 2) {
                    if (use_lo) {
                        uint32_t al[4];
                        ldsm4a(al, sb + TILE_B + sw128(bo));
                        #pragma unroll
                        for (int ni = 0; ni < 4; ni++) {
                            mma16816(c[mi][ni], ah, bf[ni][0], bf[ni][1]);
                            mma16816(c[mi][ni], al, bf[ni][0], bf[ni][1]);
                        }
                    } else {
                        #pragma unroll
                        for (int ni = 0; ni < 4; ni++)
                            mma16816(c[mi][ni], ah, bf[ni][0], bf[ni][1]);
                    }
                } else {
                    #pragma unroll
                    for (int ni = 0; ni < 4; ni++)
                        mma16816(c[mi][ni], ah, bf[ni][0], bf[ni][1]);
                }
            }
        }
    }

    // epilogue
    #pragma unroll
    for (int mi = 0; mi < 4; mi++) {
        #pragma unroll
        for (int hf = 0; hf < 2; hf++) {
            const int row = bm + wm + mi * 16 + group + hf * 8;
            #pragma unroll
            for (int ni = 0; ni < 4; ni++) {
                const int col = bn + wn + ni * 8 + t4 * 2;
                float v0 = c[mi][ni][hf * 2 + 0];
                float v1 = c[mi][ni][hf * 2 + 1];
                if (EPI == 1) {
                    float2 rr = *(const float2*)(R + (size_t)row * N + col);
                    float2 o; o.x = v0 + rr.x; o.y = v1 + rr.y;
                    *(float2*)(C + (size_t)row * N + col) = o;
                } else if (EPI == 2) {
                    v0 = 0.5f * v0 * (1.0f + erff(v0 * 0.70710678118654752f));
                    v1 = 0.5f * v1 * (1.0f + erff(v1 * 0.70710678118654752f));
                    *(__half2*)(Ohi + (size_t)row * N + col) =
                        __floats2half2_rn(v0, v1);
                } else if (EPI == 5) {
                    const int seg = col >> 10;
                    const int lc  = col & 1023;
                    const size_t di = ((size_t)seg * ROWS + row) * DD + lc;
                    __half h0 = __float2half_rn(v0), h1 = __float2half_rn(v1);
                    *(__half2*)(Ohi + di) = __halves2half2(h0, h1);
                    if (seg < 2) {   // V consumer never reads lo
                        *(__half2*)(Olo + di) = __halves2half2(
                            __float2half_rn(v0 - __half2float(h0)),
                            __float2half_rn(v1 - __half2float(h1)));
                    }
                } else {  // EPI == 3
                    float2 cc = *(const float2*)(C + (size_t)row * N + col);
                    float2 o; o.x = v0 + cc.x; o.y = v1 + cc.y;
                    *(float2*)(C + (size_t)row * N + col) = o;
                }
            }
        }
    }
}

// ---------------------------------------------------------------------------
// Tensor-core causal flash attention (R8 version).
// 256 thr, 8 warps x 16 q-rows; 64-key tiles (Kh,Kl,Vh) double-buffered;
// S = QhKh + QlKh + QhKl; P@Vh only. Output: hi fp16 only.
// ---------------------------------------------------------------------------
#define ATS 72
#define QBUF (128 * ATS)
#define KVT  (64 * ATS)
#define KVSTG3 (3 * KVT)
#define ASMEM ((2u * KVSTG3 + 2u * QBUF) * sizeof(__half))   // 92160 B

__global__ __launch_bounds__(256) void attn_tc(
    const __half* __restrict__ Qh, const __half* __restrict__ Ql,
    const __half* __restrict__ Kh, const __half* __restrict__ Kl,
    const __half* __restrict__ Vh,
    __half* __restrict__ Ohi)
{
    extern __shared__ __half sm[];
    __half* sKV = sm;                  // [2][KVSTG3]
    __half* sQh = sm + 2 * KVSTG3;
    __half* sQl = sQh + QBUF;

    const int tid  = threadIdx.x;
    const int lane = tid & 31;
    const int warp = tid >> 5;
    const int wrow = warp * 16;
    const int group = lane >> 2;
    const int t4    = lane & 3;

    const int qtile = gridDim.x - 1 - blockIdx.x;   // long blocks first
    const int bh = blockIdx.y;
    const int b = bh >> 4, h = bh & 15;
    const int qbase = qtile * 128;
    const int hoff  = h * DHH;
    const size_t tokb = (size_t)b * TT;

    const int a_row = (lane & 7) + ((lane >> 3) & 1) * 8;
    const int a_k   = (lane >> 4) * 8;
    const int b_row = (lane & 7) + ((lane >> 4) & 1) * 8;
    const int b_k   = ((lane >> 3) & 1) * 8;
    const int v_row = (lane & 7) + ((lane >> 3) & 1) * 8;
    const int v_col = (lane >> 4) * 8;

    // group 0: Q (hi + lo)
    #pragma unroll
    for (int i = 0; i < 8; i++) {
        const int buf = i >> 2;
        const int within = (i & 3) * 256 + tid;
        const int row = within >> 3;
        const int c8  = (within & 7) * 8;
        const __half* src = (buf == 0 ? Qh : Ql) + (tokb + qbase + row) * DD + hoff + c8;
        cp_async16p((buf == 0 ? sQh : sQl) + row * ATS + c8, src);
    }
    asm volatile("cp.async.commit_group;\n");

    #define KV_LOAD(st, key0)                                                        \
    {                                                                                \
        _Pragma("unroll")                                                            \
        for (int i = 0; i < 6; i++) {                                                \
            const int tile = i >> 1;                                                 \
            const int row  = (i & 1) * 32 + (tid >> 3);                              \
            const int c8   = (tid & 7) * 8;                                          \
            const __half* src = (tile == 0 ? Kh : tile == 1 ? Kl : Vh)               \
                                + (tokb + (key0) + row) * DD + hoff + c8;            \
            cp_async16p(&sKV[(st) * KVSTG3 + tile * KVT + row * ATS + c8], src);     \
        }                                                                            \
        asm volatile("cp.async.commit_group;\n");                                    \
    }

    KV_LOAD(0, 0)                                // group 1
    asm volatile("cp.async.wait_group 1;\n");    // Q done
    __syncthreads();

    uint32_t qfh[4][4], qfl[4][4];
    #pragma unroll
    for (int kc = 0; kc < 4; kc++) {
        const int off = (wrow + a_row) * ATS + kc * 16 + a_k;
        ldsm4(qfh[kc], &sQh[off]);
        ldsm4(qfl[kc], &sQl[off]);
    }

    float o[8][4];
    #pragma unroll
    for (int ni = 0; ni < 8; ni++)
        #pragma unroll
        for (int f = 0; f < 4; f++) o[ni][f] = 0.f;
    float m0 = -INFINITY, m1 = -INFINITY, l0 = 0.f, l1 = 0.f;

    const float SC2 = 0.125f * 1.4426950408889634f;
    const int nkt = 2 * qtile + 2;

    for (int kt = 0; kt < nkt; kt++) {
        const int st = kt & 1;
        asm volatile("cp.async.wait_group 0;\n");   // kv(kt) done
        __syncthreads();
        if (kt + 1 < nkt) KV_LOAD(st ^ 1, (kt + 1) * 64)

        const __half* pKh = &sKV[st * KVSTG3 + 0 * KVT];
        const __half* pKl = &sKV[st * KVSTG3 + 1 * KVT];
        const __half* pVh = &sKV[st * KVSTG3 + 2 * KVT];

        float s[8][4];
        #pragma unroll
        for (int ni = 0; ni < 8; ni++)
            #pragma unroll
            for (int f = 0; f < 4; f++) s[ni][f] = 0.f;

        #pragma unroll
        for (int kc = 0; kc < 4; kc++) {
            #pragma unroll
            for (int ntp = 0; ntp < 4; ntp++) {
                uint32_t rh[4], rl[4];
                const int off = (ntp * 16 + b_row) * ATS + kc * 16 + b_k;
                ldsm4(rh, pKh + off);
                ldsm4(rl, pKl + off);
                mma16816(s[2*ntp+0], qfh[kc], rh[0], rh[1]);
                mma16816(s[2*ntp+1], qfh[kc], rh[2], rh[3]);
                mma16816(s[2*ntp+0], qfl[kc], rh[0], rh[1]);
                mma16816(s[2*ntp+1], qfl[kc], rh[2], rh[3]);
                mma16816(s[2*ntp+0], qfh[kc], rl[0], rl[1]);
                mma16816(s[2*ntp+1], qfh[kc], rl[2], rl[3]);
            }
        }

        const int r0 = qbase + wrow + group;
        const int r1 = r0 + 8;
        const bool needmask = (kt * 64 + 63) > (qbase + wrow);
        #pragma unroll
        for (int ni = 0; ni < 8; ni++) {
            #pragma unroll
            for (int f = 0; f < 4; f++) s[ni][f] *= SC2;
            if (needmask) {
                const int col = kt * 64 + ni * 8 + t4 * 2;
                if (col > r0)     s[ni][0] = -1e30f;
                if (col + 1 > r0) s[ni][1] = -1e30f;
                if (col > r1)     s[ni][2] = -1e30f;
                if (col + 1 > r1) s[ni][3] = -1e30f;
            }
        }

        float rm0 = -INFINITY, rm1 = -INFINITY;
        #pragma unroll
        for (int ni = 0; ni < 8; ni++) {
            rm0 = fmaxf(rm0, fmaxf(s[ni][0], s[ni][1]));
            rm1 = fmaxf(rm1, fmaxf(s[ni][2], s[ni][3]));
        }
        rm0 = fmaxf(rm0, __shfl_xor_sync(0xffffffff, rm0, 1));
        rm0 = fmaxf(rm0, __shfl_xor_sync(0xffffffff, rm0, 2));
        rm1 = fmaxf(rm1, __shfl_xor_sync(0xffffffff, rm1, 1));
        rm1 = fmaxf(rm1, __shfl_xor_sync(0xffffffff, rm1, 2));

        const float nm0 = fmaxf(m0, rm0), nm1 = fmaxf(m1, rm1);
        const float al0 = exp2f(m0 - nm0), al1 = exp2f(m1 - nm1);
        l0 *= al0; l1 *= al1;
        m0 = nm0; m1 = nm1;
        #pragma unroll
        for (int ni = 0; ni < 8; ni++) {
            o[ni][0] *= al0; o[ni][1] *= al0;
            o[ni][2] *= al1; o[ni][3] *= al1;
        }

        uint32_t pf[8][2];
        float la0 = 0.f, la1 = 0.f;
        #pragma unroll
        for (int ni = 0; ni < 8; ni++) {
            __half2 t0 = __floats2half2_rn(fmaxf(s[ni][0] - m0, -60.f),
                                           fmaxf(s[ni][1] - m0, -60.f));
            __half2 t1 = __floats2half2_rn(fmaxf(s[ni][2] - m1, -60.f),
                                           fmaxf(s[ni][3] - m1, -60.f));
            uint32_t p0 = h2ex2(*(uint32_t*)&t0);
            uint32_t p1 = h2ex2(*(uint32_t*)&t1);
            pf[ni][0] = p0; pf[ni][1] = p1;
            float2 f0 = __half22float2(*(__half2*)&p0);
            float2 f1 = __half22float2(*(__half2*)&p1);
            la0 += f0.x + f0.y;
            la1 += f1.x + f1.y;
        }
        la0 += __shfl_xor_sync(0xffffffff, la0, 1);
        la0 += __shfl_xor_sync(0xffffffff, la0, 2);
        la1 += __shfl_xor_sync(0xffffffff, la1, 1);
        la1 += __shfl_xor_sync(0xffffffff, la1, 2);
        l0 += la0; l1 += la1;

        #pragma unroll
        for (int kc = 0; kc < 4; kc++) {
            uint32_t a[4] = { pf[2*kc][0], pf[2*kc][1], pf[2*kc+1][0], pf[2*kc+1][1] };
            #pragma unroll
            for (int ntp = 0; ntp < 4; ntp++) {
                uint32_t rh[4];
                const int off = (kc * 16 + v_row) * ATS + ntp * 16 + v_col;
                ldsm4t(rh, pVh + off);
                mma16816(o[2*ntp+0], a, rh[0], rh[1]);
                mma16816(o[2*ntp+1], a, rh[2], rh[3]);
            }
        }
    }

    const float il0 = 1.0f / l0, il1 = 1.0f / l1;
    const size_t gr0 = (tokb + qbase + wrow + group) * DD + hoff;
    const size_t gr1 = gr0 + 8 * DD;
    #pragma unroll
    for (int ni = 0; ni < 8; ni++) {
        const int col = ni * 8 + t4 * 2;
        *(__half2*)(Ohi + gr0 + col) = __floats2half2_rn(o[ni][0] * il0, o[ni][1] * il0);
        *(__half2*)(Ohi + gr1 + col) = __floats2half2_rn(o[ni][2] * il1, o[ni][3] * il1);
    }
}

// ---------------------------------------------------------------------------
// kernel_launch
// ---------------------------------------------------------------------------
extern "C" void kernel_launch(void* const* d_in, const int* in_sizes, int n_in,
                              void* d_out, int out_size)
{
    const float* x     = (const float*)d_in[0];
    const float* ln1_g = (const float*)d_in[2];
    const float* ln1_b = (const float*)d_in[3];
    const float* ln2_g = (const float*)d_in[4];
    const float* ln2_b = (const float*)d_in[5];
    const float* Wq    = (const float*)d_in[6];
    const float* Wk    = (const float*)d_in[7];
    const float* Wv    = (const float*)d_in[8];
    const float* Wo    = (const float*)d_in[9];
    const float* Wff1  = (const float*)d_in[10];
    const float* Wff2  = (const float*)d_in[11];
    float* out = (float*)d_out;

    unsigned char* base = nullptr;
    cudaGetSymbolAddress((void**)&base, g_scratch);
    size_t off = 0;
    auto carve = [&](size_t bytes) { void* p = base + off; off += bytes; return p; };

    __half* qkv_hi = (__half*)carve((size_t)3 * SEG * 2);
    __half* qkv_lo = (__half*)carve((size_t)3 * SEG * 2);   // V segment unused
    __half* h_hi   = (__half*)carve((size_t)SEG * 2);
    __half* h_lo   = (__half*)carve((size_t)SEG * 2);
    __half* att_hi = (__half*)carve((size_t)SEG * 2);
    __half* ff_hi  = (__half*)carve((size_t)ROWS * FFD * 2);
    __half* Wqkv_h = (__half*)carve((size_t)3 * DD * DD * 2);
    __half* Wo_h   = (__half*)carve((size_t)DD * DD * 2);
    __half* Wff_h  = (__half*)carve((size_t)2 * FFD * DD * 2);

    __half* Wf1_h = Wff_h;
    __half* Wf2_h = Wff_h + (size_t)FFD * DD;

    const uint32_t SM2 = 2u * 3u * TILE_B;   // NLIMB=2: 2 stages x 48KB = 98304 B
    const uint32_t SM1 = 2u * 2u * TILE_B;   // NLIMB=1: 2 stages x 32KB = 65536 B (3 CTAs/SM)
    cudaFuncSetAttribute((const void*)gemm_f16<5,2>, cudaFuncAttributeMaxDynamicSharedMemorySize, (int)SM2);
    cudaFuncSetAttribute((const void*)gemm_f16<1,1>, cudaFuncAttributeMaxDynamicSharedMemorySize, (int)SM1);
    cudaFuncSetAttribute((const void*)gemm_f16<2,1>, cudaFuncAttributeMaxDynamicSharedMemorySize, (int)SM1);
    cudaFuncSetAttribute((const void*)gemm_f16<3,1>, cudaFuncAttributeMaxDynamicSharedMemorySize, (int)SM1);
    cudaFuncSetAttribute((const void*)attn_tc, cudaFuncAttributeMaxDynamicSharedMemorySize, (int)ASMEM);

    // launches ordered so ncu -s 5 captures launch #6 = Wo GEMM
    w2h_attn<<<4 * DD * DD / 1024, 256>>>(Wq, Wk, Wv, Wo, Wqkv_h);
    w2h_ff<<<2 * FFD * DD / 1024, 256>>>(Wff1, Wff2, Wff_h);

    ln_split_kernel<<<ROWS, 256>>>(x, ln1_g, ln1_b, h_hi, h_lo);

    // fused QKV: N = 3072, split A on Q/K blocks only
    gemm_f16<5,2><<<dim3(3 * DD / GN, ROWS / GM), 256, SM2>>>(
        h_hi, h_lo, Wqkv_h, nullptr, nullptr, qkv_hi, qkv_lo, ROWS, 3 * DD, DD);

    attn_tc<<<dim3(TT / 128, BB * HH), 256, ASMEM>>>(
        qkv_hi, qkv_lo, qkv_hi + SEG, qkv_lo + SEG, qkv_hi + 2 * SEG, att_hi);

    gemm_f16<1,1><<<dim3(DD / GN, ROWS / GM), 256, SM1>>>(
        att_hi, nullptr, Wo_h, out, x, nullptr, nullptr, ROWS, DD, DD);

    ln_split_kernel<<<ROWS, 256>>>(out, ln2_g, ln2_b, h_hi, h_lo);

    gemm_f16<2,1><<<dim3(FFD / GN, ROWS / GM), 256, SM1>>>(
        h_hi, nullptr, Wf1_h, nullptr, nullptr, ff_hi, nullptr, ROWS, FFD, DD);

    gemm_f16<3,1><<<dim3(DD / GN, ROWS / GM), 256, SM1>>>(
        ff_hi, nullptr, Wf2_h, out, nullptr, nullptr, nullptr, ROWS, DD, FFD);
}

// round 12
// speedup vs baseline: 1.0927x; 1.0065x over previous
#include <cuda_runtime.h>
#include <cuda_fp16.h>
#include <math.h>
#include <stdint.h>

// Problem constants
#define BB   2
#define TT   2048
#define DD   1024
#define HH   16
#define DHH  64
#define FFD  4096
#define ROWS (BB*TT)          // 4096
#define SEG  (ROWS * DD)      // 4194304 elements
#define EPSF 1e-5f

__device__ __align__(256) unsigned char g_scratch[190u * 1024u * 1024u];

// ---------------------------------------------------------------------------
// helpers
// ---------------------------------------------------------------------------
__device__ __forceinline__ uint32_t smem_u32(const void* p) {
    uint32_t a;
    asm("{ .reg .u64 t; cvta.to.shared.u64 t, %1; cvt.u32.u64 %0, t; }" : "=r"(a) : "l"(p));
    return a;
}
__device__ __forceinline__ uint32_t sw128(uint32_t bo) {
    return bo ^ ((bo >> 3) & 0x70);
}
__device__ __forceinline__ void cp_async16(uint32_t smem_dst, const void* gmem_src) {
    asm volatile("cp.async.cg.shared.global [%0], [%1], 16;\n" :: "r"(smem_dst), "l"(gmem_src));
}
__device__ __forceinline__ void cp_async16p(void* smem_dst, const void* gmem_src) {
    uint32_t s = smem_u32(smem_dst);
    asm volatile("cp.async.cg.shared.global [%0], [%1], 16;\n" :: "r"(s), "l"(gmem_src));
}
__device__ __forceinline__ void ldsm4a(uint32_t* r, uint32_t a) {
    asm volatile("ldmatrix.sync.aligned.m8n8.x4.shared.b16 {%0,%1,%2,%3}, [%4];"
        : "=r"(r[0]), "=r"(r[1]), "=r"(r[2]), "=r"(r[3]) : "r"(a));
}
__device__ __forceinline__ void ldsm4(uint32_t* r, const __half* p) {
    ldsm4a(r, smem_u32(p));
}
__device__ __forceinline__ void ldsm4t(uint32_t* r, const __half* p) {
    uint32_t a = smem_u32(p);
    asm volatile("ldmatrix.sync.aligned.m8n8.x4.trans.shared.b16 {%0,%1,%2,%3}, [%4];"
        : "=r"(r[0]), "=r"(r[1]), "=r"(r[2]), "=r"(r[3]) : "r"(a));
}
__device__ __forceinline__ void mma16816(float* c, const uint32_t* a, uint32_t b0, uint32_t b1) {
    asm volatile(
        "mma.sync.aligned.m16n8k16.row.col.f32.f16.f16.f32 "
        "{%0,%1,%2,%3}, {%4,%5,%6,%7}, {%8,%9}, {%0,%1,%2,%3};"
        : "+f"(c[0]), "+f"(c[1]), "+f"(c[2]), "+f"(c[3])
        : "r"(a[0]), "r"(a[1]), "r"(a[2]), "r"(a[3]), "r"(b0), "r"(b1));
}
__device__ __forceinline__ uint32_t h2ex2(uint32_t a) {
    uint32_t d;
    asm("ex2.approx.f16x2 %0, %1;" : "=r"(d) : "r"(a));
    return d;
}

// ---------------------------------------------------------------------------
// weight conversion
// ---------------------------------------------------------------------------
__global__ __launch_bounds__(256) void w2h_attn(
    const float* __restrict__ s0, const float* __restrict__ s1,
    const float* __restrict__ s2, const float* __restrict__ s3,
    __half* __restrict__ dst)
{
    const size_t idx = ((size_t)blockIdx.x * 256 + threadIdx.x) * 4;
    const int seg = (int)(idx >> 20);
    const float* s = (seg == 0) ? s0 : (seg == 1) ? s1 : (seg == 2) ? s2 : s3;
    float4 v = *(const float4*)(s + (idx & 0xFFFFF));
    *(__half2*)(dst + idx)     = __floats2half2_rn(v.x, v.y);
    *(__half2*)(dst + idx + 2) = __floats2half2_rn(v.z, v.w);
}
__global__ __launch_bounds__(256) void w2h_ff(
    const float* __restrict__ s0, const float* __restrict__ s1,
    __half* __restrict__ dst)
{
    const size_t idx = ((size_t)blockIdx.x * 256 + threadIdx.x) * 4;
    const int seg = (int)(idx >> 22);
    const float* s = (seg == 0) ? s0 : s1;
    float4 v = *(const float4*)(s + (idx & 0x3FFFFF));
    *(__half2*)(dst + idx)     = __floats2half2_rn(v.x, v.y);
    *(__half2*)(dst + idx + 2) = __floats2half2_rn(v.z, v.w);
}

// ---------------------------------------------------------------------------
// LayerNorm -> fp16 (hi always, lo optional)
// ---------------------------------------------------------------------------
template<bool WRITE_LO>
__global__ __launch_bounds__(256) void ln_split_kernel(
    const float* __restrict__ x, const float* __restrict__ g,
    const float* __restrict__ b, __half* __restrict__ ohi, __half* __restrict__ olo)
{
    const int row = blockIdx.x;
    const int tid = threadIdx.x;
    const float* xr = x + (size_t)row * DD;

    float4 v = *(const float4*)(xr + tid * 4);
    float s  = v.x + v.y + v.z + v.w;
    float ss = v.x * v.x + v.y * v.y + v.z * v.z + v.w * v.w;

    #pragma unroll
    for (int off = 16; off > 0; off >>= 1) {
        s  += __shfl_xor_sync(0xffffffff, s,  off);
        ss += __shfl_xor_sync(0xffffffff, ss, off);
    }
    __shared__ float sbuf[8], ssbuf[8];
    const int warp = tid >> 5, lane = tid & 31;
    if (lane == 0) { sbuf[warp] = s; ssbuf[warp] = ss; }
    __syncthreads();
    float S = 0.f, SS = 0.f;
    #pragma unroll
    for (int i = 0; i < 8; i++) { S += sbuf[i]; SS += ssbuf[i]; }

    const float mu  = S * (1.0f / DD);
    const float var = SS * (1.0f / DD) - mu * mu;
    const float rs  = rsqrtf(var + EPSF);

    float4 gg = *(const float4*)(g + tid * 4);
    float4 bb = *(const float4*)(b + tid * 4);
    float y0 = (v.x - mu) * rs * gg.x + bb.x;
    float y1 = (v.y - mu) * rs * gg.y + bb.y;
    float y2 = (v.z - mu) * rs * gg.z + bb.z;
    float y3 = (v.w - mu) * rs * gg.w + bb.w;

    __half h0 = __float2half_rn(y0), h1 = __float2half_rn(y1);
    __half h2 = __float2half_rn(y2), h3 = __float2half_rn(y3);
    const size_t base = (size_t)row * DD + tid * 4;
    *(__half2*)(ohi + base)     = __halves2half2(h0, h1);
    *(__half2*)(ohi + base + 2) = __halves2half2(h2, h3);
    if (WRITE_LO) {
        *(__half2*)(olo + base)     = __halves2half2(
            __float2half_rn(y0 - __half2float(h0)), __float2half_rn(y1 - __half2float(h1)));
        *(__half2*)(olo + base + 2) = __halves2half2(
            __float2half_rn(y2 - __half2float(h2)), __float2half_rn(y3 - __half2float(h3)));
    }
}

// ---------------------------------------------------------------------------
// fp16 GEMM: C[M,N] = A[M,K] @ W[N,K]^T, A = Ah (+ Al if NLIMB==2)
// 128x128 tile, BK=64 (128B rows, XOR-swizzled), 2-stage cp.async,
// ONE __syncthreads per k64 iter. 8 warps (2x4), 64x32 per warp.
// EPI: 1 C=acc+R(f32), 2 gelu->Ohi, 3 C+=acc, 4 hi-store,
//      5 segmented split (Q|K fused: col>>10 picks segment, hi+lo)
// ---------------------------------------------------------------------------
#define GM 128
#define GN 128
#define GK 64
#define TILE_B 16384u

template<int EPI, int NLIMB>
__global__ __launch_bounds__(256) void gemm_f16(
    const __half* __restrict__ Ah, const __half* __restrict__ Al,
    const __half* __restrict__ Wh, float* __restrict__ C,
    const float* __restrict__ R, __half* __restrict__ Ohi, __half* __restrict__ Olo,
    int M, int N, int K)
{
    extern __shared__ unsigned char smraw[];
    const uint32_t smb = smem_u32(smraw);

    constexpr int PL = NLIMB + 1;                 // planes per stage (A limbs + W)
    constexpr uint32_t STAGEB = PL * TILE_B;

    const int tid   = threadIdx.x;
    const int lane  = tid & 31;
    const int warp  = tid >> 5;
    const int wm    = (warp >> 2) * 64;
    const int wn    = (warp & 3) * 32;
    const int group = lane >> 2;
    const int t4    = lane & 3;

    const int bm = blockIdx.y * GM;
    const int bn = blockIdx.x * GN;

    const int a_row = (lane & 7) + ((lane >> 3) & 1) * 8;
    const int a_k   = (lane >> 4) * 8;
    const int b_row = (lane & 7) + ((lane >> 4) & 1) * 8;
    const int b_k   = ((lane >> 3) & 1) * 8;

    float c[4][4][4];
    #pragma unroll
    for (int mi = 0; mi < 4; mi++)
        #pragma unroll
        for (int ni = 0; ni < 4; ni++)
            #pragma unroll
            for (int f = 0; f < 4; f++) c[mi][ni][f] = 0.f;

    const int KT = K / GK;

    #define STAGE_LOAD(st, k0)                                                      \
    {                                                                               \
        const uint32_t sb_ = smb + (st) * STAGEB;                                   \
        _Pragma("unroll")                                                           \
        for (int i = 0; i < 4 * PL; i++) {                                          \
            const int pl  = i >> 2;                                                 \
            const int id  = (i & 3) * 256 + tid;                                    \
            const int row = id >> 3;                                                \
            const int kq  = id & 7;                                                 \
            const uint32_t bo = row * 128 + kq * 16;                                \
            const __half* src; size_t gr;                                           \
            if (pl == NLIMB)      { src = Wh; gr = (size_t)(bn + row) * K; }        \
            else if (pl == 0)     { src = Ah; gr = (size_t)(bm + row) * K; }        \
            else                  { src = Al; gr = (size_t)(bm + row) * K; }        \
            cp_async16(sb_ + pl * TILE_B + sw128(bo), src + gr + (k0) + kq * 8);    \
        }                                                                           \
        asm volatile("cp.async.commit_group;\n");                                   \
    }

    STAGE_LOAD(0, 0)

    for (int kt = 0; kt < KT; kt++) {
        asm volatile("cp.async.wait_group 0;\n");
        __syncthreads();                       // data visible + prev stage free
        if (kt + 1 < KT) STAGE_LOAD((kt + 1) & 1, (kt + 1) * GK)

        const uint32_t sb = smb + (kt & 1) * STAGEB;
        #pragma unroll
        for (int ks = 0; ks < 4; ks++) {
            uint32_t bf[4][2];
            #pragma unroll
            for (int ng = 0; ng < 2; ng++) {
                uint32_t r[4];
                ldsm4a(r, sb + NLIMB * TILE_B +
                       sw128((wn + ng * 16 + b_row) * 128 + (ks * 16 + b_k) * 2));
                bf[2 * ng + 0][0] = r[0]; bf[2 * ng + 0][1] = r[1];
                bf[2 * ng + 1][0] = r[2]; bf[2 * ng + 1][1] = r[3];
            }
            #pragma unroll
            for (int mi = 0; mi < 4; mi++) {
                uint32_t ah[4];
                const uint32_t bo = (wm + mi * 16 + a_row) * 128 + (ks * 16 + a_k) * 2;
                ldsm4a(ah, sb + sw128(bo));
                if (NLIMB == 2) {
                    uint32_t al[4];
                    ldsm4a(al, sb + TILE_B + sw128(bo));
                    #pragma unroll
                    for (int ni = 0; ni < 4; ni++) {
                        mma16816(c[mi][ni], ah, bf[ni][0], bf[ni][1]);
                        mma16816(c[mi][ni], al, bf[ni][0], bf[ni][1]);
                    }
                } else {
                    #pragma unroll
                    for (int ni = 0; ni < 4; ni++)
                        mma16816(c[mi][ni], ah, bf[ni][0], bf[ni][1]);
                }
            }
        }
    }

    // epilogue
    #pragma unroll
    for (int mi = 0; mi < 4; mi++) {
        #pragma unroll
        for (int hf = 0; hf < 2; hf++) {
            const int row = bm + wm + mi * 16 + group + hf * 8;
            #pragma unroll
            for (int ni = 0; ni < 4; ni++) {
                const int col = bn + wn + ni * 8 + t4 * 2;
                float v0 = c[mi][ni][hf * 2 + 0];
                float v1 = c[mi][ni][hf * 2 + 1];
                if (EPI == 1) {
                    float2 rr = *(const float2*)(R + (size_t)row * N + col);
                    float2 o; o.x = v0 + rr.x; o.y = v1 + rr.y;
                    *(float2*)(C + (size_t)row * N + col) = o;
                } else if (EPI == 2) {
                    v0 = 0.5f * v0 * (1.0f + erff(v0 * 0.70710678118654752f));
                    v1 = 0.5f * v1 * (1.0f + erff(v1 * 0.70710678118654752f));
                    *(__half2*)(Ohi + (size_t)row * N + col) =
                        __floats2half2_rn(v0, v1);
                } else if (EPI == 4) {
                    *(__half2*)(Ohi + (size_t)row * N + col) =
                        __floats2half2_rn(v0, v1);
                } else if (EPI == 5) {
                    const int seg = col >> 10;
                    const int lc  = col & 1023;
                    const size_t di = ((size_t)seg * ROWS + row) * DD + lc;
                    __half h0 = __float2half_rn(v0), h1 = __float2half_rn(v1);
                    *(__half2*)(Ohi + di) = __halves2half2(h0, h1);
                    *(__half2*)(Olo + di) = __halves2half2(
                        __float2half_rn(v0 - __half2float(h0)),
                        __float2half_rn(v1 - __half2float(h1)));
                } else {  // EPI == 3
                    float2 cc = *(const float2*)(C + (size_t)row * N + col);
                    float2 o; o.x = v0 + cc.x; o.y = v1 + cc.y;
                    *(float2*)(C + (size_t)row * N + col) = o;
                }
            }
        }
    }
}

// ---------------------------------------------------------------------------
// Tensor-core causal flash attention (R8/R11 version, unchanged).
// ---------------------------------------------------------------------------
#define ATS 72
#define QBUF (128 * ATS)
#define KVT  (64 * ATS)
#define KVSTG3 (3 * KVT)
#define ASMEM ((2u * KVSTG3 + 2u * QBUF) * sizeof(__half))   // 92160 B

__global__ __launch_bounds__(256) void attn_tc(
    const __half* __restrict__ Qh, const __half* __restrict__ Ql,
    const __half* __restrict__ Kh, const __half* __restrict__ Kl,
    const __half* __restrict__ Vh,
    __half* __restrict__ Ohi)
{
    extern __shared__ __half sm[];
    __half* sKV = sm;                  // [2][KVSTG3]
    __half* sQh = sm + 2 * KVSTG3;
    __half* sQl = sQh + QBUF;

    const int tid  = threadIdx.x;
    const int lane = tid & 31;
    const int warp = tid >> 5;
    const int wrow = warp * 16;
    const int group = lane >> 2;
    const int t4    = lane & 3;

    const int qtile = gridDim.x - 1 - blockIdx.x;   // long blocks first
    const int bh = blockIdx.y;
    const int b = bh >> 4, h = bh & 15;
    const int qbase = qtile * 128;
    const int hoff  = h * DHH;
    const size_t tokb = (size_t)b * TT;

    const int a_row = (lane & 7) + ((lane >> 3) & 1) * 8;
    const int a_k   = (lane >> 4) * 8;
    const int b_row = (lane & 7) + ((lane >> 4) & 1) * 8;
    const int b_k   = ((lane >> 3) & 1) * 8;
    const int v_row = (lane & 7) + ((lane >> 3) & 1) * 8;
    const int v_col = (lane >> 4) * 8;

    // group 0: Q (hi + lo)
    #pragma unroll
    for (int i = 0; i < 8; i++) {
        const int buf = i >> 2;
        const int within = (i & 3) * 256 + tid;
        const int row = within >> 3;
        const int c8  = (within & 7) * 8;
        const __half* src = (buf == 0 ? Qh : Ql) + (tokb + qbase + row) * DD + hoff + c8;
        cp_async16p((buf == 0 ? sQh : sQl) + row * ATS + c8, src);
    }
    asm volatile("cp.async.commit_group;\n");

    #define KV_LOAD(st, key0)                                                        \
    {                                                                                \
        _Pragma("unroll")                                                            \
        for (int i = 0; i < 6; i++) {                                                \
            const int tile = i >> 1;                                                 \
            const int row  = (i & 1) * 32 + (tid >> 3);                              \
            const int c8   = (tid & 7) * 8;                                          \
            const __half* src = (tile == 0 ? Kh : tile == 1 ? Kl : Vh)               \
                                + (tokb + (key0) + row) * DD + hoff + c8;            \
            cp_async16p(&sKV[(st) * KVSTG3 + tile * KVT + row * ATS + c8], src);     \
        }                                                                            \
        asm volatile("cp.async.commit_group;\n");                                    \
    }

    KV_LOAD(0, 0)                                // group 1
    asm volatile("cp.async.wait_group 1;\n");    // Q done
    __syncthreads();

    uint32_t qfh[4][4], qfl[4][4];
    #pragma unroll
    for (int kc = 0; kc < 4; kc++) {
        const int off = (wrow + a_row) * ATS + kc * 16 + a_k;
        ldsm4(qfh[kc], &sQh[off]);
        ldsm4(qfl[kc], &sQl[off]);
    }

    float o[8][4];
    #pragma unroll
    for (int ni = 0; ni < 8; ni++)
        #pragma unroll
        for (int f = 0; f < 4; f++) o[ni][f] = 0.f;
    float m0 = -INFINITY, m1 = -INFINITY, l0 = 0.f, l1 = 0.f;

    const float SC2 = 0.125f * 1.4426950408889634f;
    const int nkt = 2 * qtile + 2;

    for (int kt = 0; kt < nkt; kt++) {
        const int st = kt & 1;
        asm volatile("cp.async.wait_group 0;\n");   // kv(kt) done
        __syncthreads();
        if (kt + 1 < nkt) KV_LOAD(st ^ 1, (kt + 1) * 64)

        const __half* pKh = &sKV[st * KVSTG3 + 0 * KVT];
        const __half* pKl = &sKV[st * KVSTG3 + 1 * KVT];
        const __half* pVh = &sKV[st * KVSTG3 + 2 * KVT];

        float s[8][4];
        #pragma unroll
        for (int ni = 0; ni < 8; ni++)
            #pragma unroll
            for (int f = 0; f < 4; f++) s[ni][f] = 0.f;

        #pragma unroll
        for (int kc = 0; kc < 4; kc++) {
            #pragma unroll
            for (int ntp = 0; ntp < 4; ntp++) {
                uint32_t rh[4], rl[4];
                const int off = (ntp * 16 + b_row) * ATS + kc * 16 + b_k;
                ldsm4(rh, pKh + off);
                ldsm4(rl, pKl + off);
                mma16816(s[2*ntp+0], qfh[kc], rh[0], rh[1]);
                mma16816(s[2*ntp+1], qfh[kc], rh[2], rh[3]);
                mma16816(s[2*ntp+0], qfl[kc], rh[0], rh[1]);
                mma16816(s[2*ntp+1], qfl[kc], rh[2], rh[3]);
                mma16816(s[2*ntp+0], qfh[kc], rl[0], rl[1]);
                mma16816(s[2*ntp+1], qfh[kc], rl[2], rl[3]);
            }
        }

        const int r0 = qbase + wrow + group;
        const int r1 = r0 + 8;
        const bool needmask = (kt * 64 + 63) > (qbase + wrow);
        #pragma unroll
        for (int ni = 0; ni < 8; ni++) {
            #pragma unroll
            for (int f = 0; f < 4; f++) s[ni][f] *= SC2;
            if (needmask) {
                const int col = kt * 64 + ni * 8 + t4 * 2;
                if (col > r0)     s[ni][0] = -1e30f;
                if (col + 1 > r0) s[ni][1] = -1e30f;
                if (col > r1)     s[ni][2] = -1e30f;
                if (col + 1 > r1) s[ni][3] = -1e30f;
            }
        }

        float rm0 = -INFINITY, rm1 = -INFINITY;
        #pragma unroll
        for (int ni = 0; ni < 8; ni++) {
            rm0 = fmaxf(rm0, fmaxf(s[ni][0], s[ni][1]));
            rm1 = fmaxf(rm1, fmaxf(s[ni][2], s[ni][3]));
        }
        rm0 = fmaxf(rm0, __shfl_xor_sync(0xffffffff, rm0, 1));
        rm0 = fmaxf(rm0, __shfl_xor_sync(0xffffffff, rm0, 2));
        rm1 = fmaxf(rm1, __shfl_xor_sync(0xffffffff, rm1, 1));
        rm1 = fmaxf(rm1, __shfl_xor_sync(0xffffffff, rm1, 2));

        const float nm0 = fmaxf(m0, rm0), nm1 = fmaxf(m1, rm1);
        const float al0 = exp2f(m0 - nm0), al1 = exp2f(m1 - nm1);
        l0 *= al0; l1 *= al1;
        m0 = nm0; m1 = nm1;
        #pragma unroll
        for (int ni = 0; ni < 8; ni++) {
            o[ni][0] *= al0; o[ni][1] *= al0;
            o[ni][2] *= al1; o[ni][3] *= al1;
        }

        uint32_t pf[8][2];
        float la0 = 0.f, la1 = 0.f;
        #pragma unroll
        for (int ni = 0; ni < 8; ni++) {
            __half2 t0 = __floats2half2_rn(fmaxf(s[ni][0] - m0, -60.f),
                                           fmaxf(s[ni][1] - m0, -60.f));
            __half2 t1 = __floats2half2_rn(fmaxf(s[ni][2] - m1, -60.f),
                                           fmaxf(s[ni][3] - m1, -60.f));
            uint32_t p0 = h2ex2(*(uint32_t*)&t0);
            uint32_t p1 = h2ex2(*(uint32_t*)&t1);
            pf[ni][0] = p0; pf[ni][1] = p1;
            float2 f0 = __half22float2(*(__half2*)&p0);
            float2 f1 = __half22float2(*(__half2*)&p1);
            la0 += f0.x + f0.y;
            la1 += f1.x + f1.y;
        }
        la0 += __shfl_xor_sync(0xffffffff, la0, 1);
        la0 += __shfl_xor_sync(0xffffffff, la0, 2);
        la1 += __shfl_xor_sync(0xffffffff, la1, 1);
        la1 += __shfl_xor_sync(0xffffffff, la1, 2);
        l0 += la0; l1 += la1;

        #pragma unroll
        for (int kc = 0; kc < 4; kc++) {
            uint32_t a[4] = { pf[2*kc][0], pf[2*kc][1], pf[2*kc+1][0], pf[2*kc+1][1] };
            #pragma unroll
            for (int ntp = 0; ntp < 4; ntp++) {
                uint32_t rh[4];
                const int off = (kc * 16 + v_row) * ATS + ntp * 16 + v_col;
                ldsm4t(rh, pVh + off);
                mma16816(o[2*ntp+0], a, rh[0], rh[1]);
                mma16816(o[2*ntp+1], a, rh[2], rh[3]);
            }
        }
    }

    const float il0 = 1.0f / l0, il1 = 1.0f / l1;
    const size_t gr0 = (tokb + qbase + wrow + group) * DD + hoff;
    const size_t gr1 = gr0 + 8 * DD;
    #pragma unroll
    for (int ni = 0; ni < 8; ni++) {
        const int col = ni * 8 + t4 * 2;
        *(__half2*)(Ohi + gr0 + col) = __floats2half2_rn(o[ni][0] * il0, o[ni][1] * il0);
        *(__half2*)(Ohi + gr1 + col) = __floats2half2_rn(o[ni][2] * il1, o[ni][3] * il1);
    }
}

// ---------------------------------------------------------------------------
// kernel_launch
// ---------------------------------------------------------------------------
extern "C" void kernel_launch(void* const* d_in, const int* in_sizes, int n_in,
                              void* d_out, int out_size)
{
    const float* x     = (const float*)d_in[0];
    const float* ln1_g = (const float*)d_in[2];
    const float* ln1_b = (const float*)d_in[3];
    const float* ln2_g = (const float*)d_in[4];
    const float* ln2_b = (const float*)d_in[5];
    const float* Wq    = (const float*)d_in[6];
    const float* Wk    = (const float*)d_in[7];
    const float* Wv    = (const float*)d_in[8];
    const float* Wo    = (const float*)d_in[9];
    const float* Wff1  = (const float*)d_in[10];
    const float* Wff2  = (const float*)d_in[11];
    float* out = (float*)d_out;

    unsigned char* base = nullptr;
    cudaGetSymbolAddress((void**)&base, g_scratch);
    size_t off = 0;
    auto carve = [&](size_t bytes) { void* p = base + off; off += bytes; return p; };

    __half* qkv_hi = (__half*)carve((size_t)3 * SEG * 2);   // q | k | v (hi)
    __half* qk_lo  = (__half*)carve((size_t)2 * SEG * 2);   // q | k (lo)
    __half* h_hi   = (__half*)carve((size_t)SEG * 2);
    __half* h_lo   = (__half*)carve((size_t)SEG * 2);
    __half* att_hi = (__half*)carve((size_t)SEG * 2);
    __half* ff_hi  = (__half*)carve((size_t)ROWS * FFD * 2);
    __half* Wqkv_h = (__half*)carve((size_t)3 * DD * DD * 2);   // Wq|Wk|Wv
    __half* Wo_h   = (__half*)carve((size_t)DD * DD * 2);       // after (w2h_attn dst)
    __half* Wff_h  = (__half*)carve((size_t)2 * FFD * DD * 2);

    __half* Wf1_h = Wff_h;
    __half* Wf2_h = Wff_h + (size_t)FFD * DD;
    __half* Wv_h  = Wqkv_h + (size_t)2 * DD * DD;

    const uint32_t SM2 = 2u * 3u * TILE_B;   // NLIMB=2: 2 stages x 48KB = 98304 B
    const uint32_t SM1 = 2u * 2u * TILE_B;   // NLIMB=1: 2 stages x 32KB = 65536 B
    cudaFuncSetAttribute((const void*)gemm_f16<5,2>, cudaFuncAttributeMaxDynamicSharedMemorySize, (int)SM2);
    cudaFuncSetAttribute((const void*)gemm_f16<1,1>, cudaFuncAttributeMaxDynamicSharedMemorySize, (int)SM1);
    cudaFuncSetAttribute((const void*)gemm_f16<2,1>, cudaFuncAttributeMaxDynamicSharedMemorySize, (int)SM1);
    cudaFuncSetAttribute((const void*)gemm_f16<3,1>, cudaFuncAttributeMaxDynamicSharedMemorySize, (int)SM1);
    cudaFuncSetAttribute((const void*)gemm_f16<4,1>, cudaFuncAttributeMaxDynamicSharedMemorySize, (int)SM1);
    cudaFuncSetAttribute((const void*)attn_tc, cudaFuncAttributeMaxDynamicSharedMemorySize, (int)ASMEM);

    // launch order: attn_tc is launch index 5 -> ncu -s 5 -c 1 profiles it
    w2h_attn<<<4 * DD * DD / 1024, 256>>>(Wq, Wk, Wv, Wo, Wqkv_h);          // 0
    w2h_ff<<<2 * FFD * DD / 1024, 256>>>(Wff1, Wff2, Wff_h);                // 1

    ln_split_kernel<true><<<ROWS, 256>>>(x, ln1_g, ln1_b, h_hi, h_lo);      // 2

    // QK fused: N = 2048, 2-limb, split store (hi+lo)
    gemm_f16<5,2><<<dim3(2 * DD / GN, ROWS / GM), 256, SM2>>>(              // 3
        h_hi, h_lo, Wqkv_h, nullptr, nullptr, qkv_hi, qk_lo, ROWS, 2 * DD, DD);

    // V: N = 1024, 1-limb, hi-only store
    gemm_f16<4,1><<<dim3(DD / GN, ROWS / GM), 256, SM1>>>(                  // 4
        h_hi, nullptr, Wv_h, nullptr, nullptr, qkv_hi + 2 * SEG, nullptr, ROWS, DD, DD);

    attn_tc<<<dim3(TT / 128, BB * HH), 256, ASMEM>>>(                       // 5 (profiled)
        qkv_hi, qk_lo, qkv_hi + SEG, qk_lo + SEG, qkv_hi + 2 * SEG, att_hi);

    gemm_f16<1,1><<<dim3(DD / GN, ROWS / GM), 256, SM1>>>(
        att_hi, nullptr, Wo_h, out, x, nullptr, nullptr, ROWS, DD, DD);

    ln_split_kernel<false><<<ROWS, 256>>>(out, ln2_g, ln2_b, h_hi, nullptr);

    gemm_f16<2,1><<<dim3(FFD / GN, ROWS / GM), 256, SM1>>>(
        h_hi, nullptr, Wf1_h, nullptr, nullptr, ff_hi, nullptr, ROWS, FFD, DD);

    gemm_f16<3,1><<<dim3(DD / GN, ROWS / GM), 256, SM1>>>(
        ff_hi, nullptr, Wf2_h, out, nullptr, nullptr, nullptr, ROWS, DD, FFD);
}

// round 13
// speedup vs baseline: 1.1219x; 1.0267x over previous
#include <cuda_runtime.h>
#include <cuda_fp16.h>
#include <math.h>
#include <stdint.h>

// Problem constants
#define BB   2
#define TT   2048
#define DD   1024
#define HH   16
#define DHH  64
#define FFD  4096
#define ROWS (BB*TT)          // 4096
#define SEG  (ROWS * DD)      // 4194304 elements
#define EPSF 1e-5f

__device__ __align__(256) unsigned char g_scratch[190u * 1024u * 1024u];

// ---------------------------------------------------------------------------
// helpers
// ---------------------------------------------------------------------------
__device__ __forceinline__ uint32_t smem_u32(const void* p) {
    uint32_t a;
    asm("{ .reg .u64 t; cvta.to.shared.u64 t, %1; cvt.u32.u64 %0, t; }" : "=r"(a) : "l"(p));
    return a;
}
__device__ __forceinline__ uint32_t sw128(uint32_t bo) {
    return bo ^ ((bo >> 3) & 0x70);
}
__device__ __forceinline__ void cp_async16(uint32_t smem_dst, const void* gmem_src) {
    asm volatile("cp.async.cg.shared.global [%0], [%1], 16;\n" :: "r"(smem_dst), "l"(gmem_src));
}
__device__ __forceinline__ void cp_async16p(void* smem_dst, const void* gmem_src) {
    uint32_t s = smem_u32(smem_dst);
    asm volatile("cp.async.cg.shared.global [%0], [%1], 16;\n" :: "r"(s), "l"(gmem_src));
}
__device__ __forceinline__ void ldsm4a(uint32_t* r, uint32_t a) {
    asm volatile("ldmatrix.sync.aligned.m8n8.x4.shared.b16 {%0,%1,%2,%3}, [%4];"
        : "=r"(r[0]), "=r"(r[1]), "=r"(r[2]), "=r"(r[3]) : "r"(a));
}
__device__ __forceinline__ void ldsm4(uint32_t* r, const __half* p) {
    ldsm4a(r, smem_u32(p));
}
__device__ __forceinline__ void ldsm4t(uint32_t* r, const __half* p) {
    uint32_t a = smem_u32(p);
    asm volatile("ldmatrix.sync.aligned.m8n8.x4.trans.shared.b16 {%0,%1,%2,%3}, [%4];"
        : "=r"(r[0]), "=r"(r[1]), "=r"(r[2]), "=r"(r[3]) : "r"(a));
}
__device__ __forceinline__ void mma16816(float* c, const uint32_t* a, uint32_t b0, uint32_t b1) {
    asm volatile(
        "mma.sync.aligned.m16n8k16.row.col.f32.f16.f16.f32 "
        "{%0,%1,%2,%3}, {%4,%5,%6,%7}, {%8,%9}, {%0,%1,%2,%3};"
        : "+f"(c[0]), "+f"(c[1]), "+f"(c[2]), "+f"(c[3])
        : "r"(a[0]), "r"(a[1]), "r"(a[2]), "r"(a[3]), "r"(b0), "r"(b1));
}
__device__ __forceinline__ uint32_t h2ex2(uint32_t a) {
    uint32_t d;
    asm("ex2.approx.f16x2 %0, %1;" : "=r"(d) : "r"(a));
    return d;
}

// ---------------------------------------------------------------------------
// weight conversion
// ---------------------------------------------------------------------------
__global__ __launch_bounds__(256) void w2h_attn(
    const float* __restrict__ s0, const float* __restrict__ s1,
    const float* __restrict__ s2, const float* __restrict__ s3,
    __half* __restrict__ dst)
{
    const size_t idx = ((size_t)blockIdx.x * 256 + threadIdx.x) * 4;
    const int seg = (int)(idx >> 20);
    const float* s = (seg == 0) ? s0 : (seg == 1) ? s1 : (seg == 2) ? s2 : s3;
    float4 v = *(const float4*)(s + (idx & 0xFFFFF));
    *(__half2*)(dst + idx)     = __floats2half2_rn(v.x, v.y);
    *(__half2*)(dst + idx + 2) = __floats2half2_rn(v.z, v.w);
}
__global__ __launch_bounds__(256) void w2h_ff(
    const float* __restrict__ s0, const float* __restrict__ s1,
    __half* __restrict__ dst)
{
    const size_t idx = ((size_t)blockIdx.x * 256 + threadIdx.x) * 4;
    const int seg = (int)(idx >> 22);
    const float* s = (seg == 0) ? s0 : s1;
    float4 v = *(const float4*)(s + (idx & 0x3FFFFF));
    *(__half2*)(dst + idx)     = __floats2half2_rn(v.x, v.y);
    *(__half2*)(dst + idx + 2) = __floats2half2_rn(v.z, v.w);
}

// ---------------------------------------------------------------------------
// LayerNorm -> fp16 (hi always, lo optional)
// ---------------------------------------------------------------------------
template<bool WRITE_LO>
__global__ __launch_bounds__(256) void ln_split_kernel(
    const float* __restrict__ x, const float* __restrict__ g,
    const float* __restrict__ b, __half* __restrict__ ohi, __half* __restrict__ olo)
{
    const int row = blockIdx.x;
    const int tid = threadIdx.x;
    const float* xr = x + (size_t)row * DD;

    float4 v = *(const float4*)(xr + tid * 4);
    float s  = v.x + v.y + v.z + v.w;
    float ss = v.x * v.x + v.y * v.y + v.z * v.z + v.w * v.w;

    #pragma unroll
    for (int off = 16; off > 0; off >>= 1) {
        s  += __shfl_xor_sync(0xffffffff, s,  off);
        ss += __shfl_xor_sync(0xffffffff, ss, off);
    }
    __shared__ float sbuf[8], ssbuf[8];
    const int warp = tid >> 5, lane = tid & 31;
    if (lane == 0) { sbuf[warp] = s; ssbuf[warp] = ss; }
    __syncthreads();
    float S = 0.f, SS = 0.f;
    #pragma unroll
    for (int i = 0; i < 8; i++) { S += sbuf[i]; SS += ssbuf[i]; }

    const float mu  = S * (1.0f / DD);
    const float var = SS * (1.0f / DD) - mu * mu;
    const float rs  = rsqrtf(var + EPSF);

    float4 gg = *(const float4*)(g + tid * 4);
    float4 bb = *(const float4*)(b + tid * 4);
    float y0 = (v.x - mu) * rs * gg.x + bb.x;
    float y1 = (v.y - mu) * rs * gg.y + bb.y;
    float y2 = (v.z - mu) * rs * gg.z + bb.z;
    float y3 = (v.w - mu) * rs * gg.w + bb.w;

    __half h0 = __float2half_rn(y0), h1 = __float2half_rn(y1);
    __half h2 = __float2half_rn(y2), h3 = __float2half_rn(y3);
    const size_t base = (size_t)row * DD + tid * 4;
    *(__half2*)(ohi + base)     = __halves2half2(h0, h1);
    *(__half2*)(ohi + base + 2) = __halves2half2(h2, h3);
    if (WRITE_LO) {
        *(__half2*)(olo + base)     = __halves2half2(
            __float2half_rn(y0 - __half2float(h0)), __float2half_rn(y1 - __half2float(h1)));
        *(__half2*)(olo + base + 2) = __halves2half2(
            __float2half_rn(y2 - __half2float(h2)), __float2half_rn(y3 - __half2float(h3)));
    }
}

// ---------------------------------------------------------------------------
// fp16 GEMM: C[M,N] = A[M,K] @ W[N,K]^T, A = Ah (+ Al if NLIMB==2)
// 128x128 tile, BK=64 (128B rows, XOR-swizzled), 2-stage cp.async,
// ONE __syncthreads per k64 iter. 8 warps (2x4), 64x32 per warp.
// EPI: 1 C=acc+R(f32), 2 gelu->Ohi, 3 C+=acc, 4 hi-store,
//      5 segmented split (Q|K fused: col>>10 picks segment, hi+lo)
// ---------------------------------------------------------------------------
#define GM 128
#define GN 128
#define GK 64
#define TILE_B 16384u

template<int EPI, int NLIMB>
__global__ __launch_bounds__(256) void gemm_f16(
    const __half* __restrict__ Ah, const __half* __restrict__ Al,
    const __half* __restrict__ Wh, float* __restrict__ C,
    const float* __restrict__ R, __half* __restrict__ Ohi, __half* __restrict__ Olo,
    int M, int N, int K)
{
    extern __shared__ unsigned char smraw[];
    const uint32_t smb = smem_u32(smraw);

    constexpr int PL = NLIMB + 1;                 // planes per stage (A limbs + W)
    constexpr uint32_t STAGEB = PL * TILE_B;

    const int tid   = threadIdx.x;
    const int lane  = tid & 31;
    const int warp  = tid >> 5;
    const int wm    = (warp >> 2) * 64;
    const int wn    = (warp & 3) * 32;
    const int group = lane >> 2;
    const int t4    = lane & 3;

    const int bm = blockIdx.y * GM;
    const int bn = blockIdx.x * GN;

    const int a_row = (lane & 7) + ((lane >> 3) & 1) * 8;
    const int a_k   = (lane >> 4) * 8;
    const int b_row = (lane & 7) + ((lane >> 4) & 1) * 8;
    const int b_k   = ((lane >> 3) & 1) * 8;

    float c[4][4][4];
    #pragma unroll
    for (int mi = 0; mi < 4; mi++)
        #pragma unroll
        for (int ni = 0; ni < 4; ni++)
            #pragma unroll
            for (int f = 0; f < 4; f++) c[mi][ni][f] = 0.f;

    const int KT = K / GK;

    #define STAGE_LOAD(st, k0)                                                      \
    {                                                                               \
        const uint32_t sb_ = smb + (st) * STAGEB;                                   \
        _Pragma("unroll")                                                           \
        for (int i = 0; i < 4 * PL; i++) {                                          \
            const int pl  = i >> 2;                                                 \
            const int id  = (i & 3) * 256 + tid;                                    \
            const int row = id >> 3;                                                \
            const int kq  = id & 7;                                                 \
            const uint32_t bo = row * 128 + kq * 16;                                \
            const __half* src; size_t gr;                                           \
            if (pl == NLIMB)      { src = Wh; gr = (size_t)(bn + row) * K; }        \
            else if (pl == 0)     { src = Ah; gr = (size_t)(bm + row) * K; }        \
            else                  { src = Al; gr = (size_t)(bm + row) * K; }        \
            cp_async16(sb_ + pl * TILE_B + sw128(bo), src + gr + (k0) + kq * 8);    \
        }                                                                           \
        asm volatile("cp.async.commit_group;\n");                                   \
    }

    STAGE_LOAD(0, 0)

    for (int kt = 0; kt < KT; kt++) {
        asm volatile("cp.async.wait_group 0;\n");
        __syncthreads();                       // data visible + prev stage free
        if (kt + 1 < KT) STAGE_LOAD((kt + 1) & 1, (kt + 1) * GK)

        const uint32_t sb = smb + (kt & 1) * STAGEB;
        #pragma unroll
        for (int ks = 0; ks < 4; ks++) {
            uint32_t bf[4][2];
            #pragma unroll
            for (int ng = 0; ng < 2; ng++) {
                uint32_t r[4];
                ldsm4a(r, sb + NLIMB * TILE_B +
                       sw128((wn + ng * 16 + b_row) * 128 + (ks * 16 + b_k) * 2));
                bf[2 * ng + 0][0] = r[0]; bf[2 * ng + 0][1] = r[1];
                bf[2 * ng + 1][0] = r[2]; bf[2 * ng + 1][1] = r[3];
            }
            #pragma unroll
            for (int mi = 0; mi < 4; mi++) {
                uint32_t ah[4];
                const uint32_t bo = (wm + mi * 16 + a_row) * 128 + (ks * 16 + a_k) * 2;
                ldsm4a(ah, sb + sw128(bo));
                if (NLIMB == 2) {
                    uint32_t al[4];
                    ldsm4a(al, sb + TILE_B + sw128(bo));
                    #pragma unroll
                    for (int ni = 0; ni < 4; ni++) {
                        mma16816(c[mi][ni], ah, bf[ni][0], bf[ni][1]);
                        mma16816(c[mi][ni], al, bf[ni][0], bf[ni][1]);
                    }
                } else {
                    #pragma unroll
                    for (int ni = 0; ni < 4; ni++)
                        mma16816(c[mi][ni], ah, bf[ni][0], bf[ni][1]);
                }
            }
        }
    }

    // epilogue
    #pragma unroll
    for (int mi = 0; mi < 4; mi++) {
        #pragma unroll
        for (int hf = 0; hf < 2; hf++) {
            const int row = bm + wm + mi * 16 + group + hf * 8;
            #pragma unroll
            for (int ni = 0; ni < 4; ni++) {
                const int col = bn + wn + ni * 8 + t4 * 2;
                float v0 = c[mi][ni][hf * 2 + 0];
                float v1 = c[mi][ni][hf * 2 + 1];
                if (EPI == 1) {
                    float2 rr = *(const float2*)(R + (size_t)row * N + col);
                    float2 o; o.x = v0 + rr.x; o.y = v1 + rr.y;
                    *(float2*)(C + (size_t)row * N + col) = o;
                } else if (EPI == 2) {
                    v0 = 0.5f * v0 * (1.0f + erff(v0 * 0.70710678118654752f));
                    v1 = 0.5f * v1 * (1.0f + erff(v1 * 0.70710678118654752f));
                    *(__half2*)(Ohi + (size_t)row * N + col) =
                        __floats2half2_rn(v0, v1);
                } else if (EPI == 4) {
                    *(__half2*)(Ohi + (size_t)row * N + col) =
                        __floats2half2_rn(v0, v1);
                } else if (EPI == 5) {
                    const int seg = col >> 10;
                    const int lc  = col & 1023;
                    const size_t di = ((size_t)seg * ROWS + row) * DD + lc;
                    __half h0 = __float2half_rn(v0), h1 = __float2half_rn(v1);
                    *(__half2*)(Ohi + di) = __halves2half2(h0, h1);
                    *(__half2*)(Olo + di) = __halves2half2(
                        __float2half_rn(v0 - __half2float(h0)),
                        __float2half_rn(v1 - __half2float(h1)));
                } else {  // EPI == 3
                    float2 cc = *(const float2*)(C + (size_t)row * N + col);
                    float2 o; o.x = v0 + cc.x; o.y = v1 + cc.y;
                    *(float2*)(C + (size_t)row * N + col) = o;
                }
            }
        }
    }
}

// ---------------------------------------------------------------------------
// Tensor-core causal flash attention — 128 threads (4 warps), 64 queries/CTA.
// Same per-warp tile (16 q-rows x 64 keys) as before; 3 CTAs/SM target.
// 64-key tiles (Kh,Kl,Vh) double-buffered; S = QhKh+QlKh+QhKl; P@Vh.
// ---------------------------------------------------------------------------
#define ATS 72
#define AQ  64                       // queries per CTA
#define QBUF (AQ * ATS)              // 4608 halves
#define KVT  (64 * ATS)              // 4608 halves
#define KVSTG3 (3 * KVT)
#define ASMEM ((2u * KVSTG3 + 2u * QBUF) * sizeof(__half))   // 73728 B

__global__ __launch_bounds__(128) void attn_tc(
    const __half* __restrict__ Qh, const __half* __restrict__ Ql,
    const __half* __restrict__ Kh, const __half* __restrict__ Kl,
    const __half* __restrict__ Vh,
    __half* __restrict__ Ohi)
{
    extern __shared__ __half sm[];
    __half* sKV = sm;                  // [2][KVSTG3]
    __half* sQh = sm + 2 * KVSTG3;
    __half* sQl = sQh + QBUF;

    const int tid  = threadIdx.x;
    const int lane = tid & 31;
    const int warp = tid >> 5;         // 0..3
    const int wrow = warp * 16;
    const int group = lane >> 2;
    const int t4    = lane & 3;

    const int qtile = gridDim.x - 1 - blockIdx.x;   // long blocks first
    const int bh = blockIdx.y;
    const int b = bh >> 4, h = bh & 15;
    const int qbase = qtile * AQ;
    const int hoff  = h * DHH;
    const size_t tokb = (size_t)b * TT;

    const int a_row = (lane & 7) + ((lane >> 3) & 1) * 8;
    const int a_k   = (lane >> 4) * 8;
    const int b_row = (lane & 7) + ((lane >> 4) & 1) * 8;
    const int b_k   = ((lane >> 3) & 1) * 8;
    const int v_row = (lane & 7) + ((lane >> 3) & 1) * 8;
    const int v_col = (lane >> 4) * 8;

    // group 0: Q (hi + lo): 2 limbs x 64 rows x 64 cols = 2x512 16B chunks,
    // 128 threads -> 8 chunks/thread
    #pragma unroll
    for (int i = 0; i < 8; i++) {
        const int buf = i >> 2;                 // 0 = hi, 1 = lo
        const int within = (i & 3) * 128 + tid; // 0..511
        const int row = within >> 3;
        const int c8  = (within & 7) * 8;
        const __half* src = (buf == 0 ? Qh : Ql) + (tokb + qbase + row) * DD + hoff + c8;
        cp_async16p((buf == 0 ? sQh : sQl) + row * ATS + c8, src);
    }
    asm volatile("cp.async.commit_group;\n");

    // KV tile: 3 planes x 64 rows x 64 cols = 3x512 chunks / 128 thr = 12 each
    #define KV_LOAD(st, key0)                                                        \
    {                                                                                \
        _Pragma("unroll")                                                            \
        for (int i = 0; i < 12; i++) {                                               \
            const int tile = i >> 2;                                                 \
            const int within = (i & 3) * 128 + tid;                                  \
            const int row  = within >> 3;                                            \
            const int c8   = (within & 7) * 8;                                       \
            const __half* src = (tile == 0 ? Kh : tile == 1 ? Kl : Vh)               \
                                + (tokb + (key0) + row) * DD + hoff + c8;            \
            cp_async16p(&sKV[(st) * KVSTG3 + tile * KVT + row * ATS + c8], src);     \
        }                                                                            \
        asm volatile("cp.async.commit_group;\n");                                    \
    }

    KV_LOAD(0, 0)                                // group 1
    asm volatile("cp.async.wait_group 1;\n");    // Q done
    __syncthreads();

    uint32_t qfh[4][4], qfl[4][4];
    #pragma unroll
    for (int kc = 0; kc < 4; kc++) {
        const int off = (wrow + a_row) * ATS + kc * 16 + a_k;
        ldsm4(qfh[kc], &sQh[off]);
        ldsm4(qfl[kc], &sQl[off]);
    }

    float o[8][4];
    #pragma unroll
    for (int ni = 0; ni < 8; ni++)
        #pragma unroll
        for (int f = 0; f < 4; f++) o[ni][f] = 0.f;
    float m0 = -INFINITY, m1 = -INFINITY, l0 = 0.f, l1 = 0.f;

    const float SC2 = 0.125f * 1.4426950408889634f;
    const int nkt = qtile + 1;

    for (int kt = 0; kt < nkt; kt++) {
        const int st = kt & 1;
        asm volatile("cp.async.wait_group 0;\n");   // kv(kt) done
        __syncthreads();
        if (kt + 1 < nkt) KV_LOAD(st ^ 1, (kt + 1) * 64)

        const __half* pKh = &sKV[st * KVSTG3 + 0 * KVT];
        const __half* pKl = &sKV[st * KVSTG3 + 1 * KVT];
        const __half* pVh = &sKV[st * KVSTG3 + 2 * KVT];

        float s[8][4];
        #pragma unroll
        for (int ni = 0; ni < 8; ni++)
            #pragma unroll
            for (int f = 0; f < 4; f++) s[ni][f] = 0.f;

        #pragma unroll
        for (int kc = 0; kc < 4; kc++) {
            #pragma unroll
            for (int ntp = 0; ntp < 4; ntp++) {
                uint32_t rh[4], rl[4];
                const int off = (ntp * 16 + b_row) * ATS + kc * 16 + b_k;
                ldsm4(rh, pKh + off);
                ldsm4(rl, pKl + off);
                mma16816(s[2*ntp+0], qfh[kc], rh[0], rh[1]);
                mma16816(s[2*ntp+1], qfh[kc], rh[2], rh[3]);
                mma16816(s[2*ntp+0], qfl[kc], rh[0], rh[1]);
                mma16816(s[2*ntp+1], qfl[kc], rh[2], rh[3]);
                mma16816(s[2*ntp+0], qfh[kc], rl[0], rl[1]);
                mma16816(s[2*ntp+1], qfh[kc], rl[2], rl[3]);
            }
        }

        const int r0 = qbase + wrow + group;
        const int r1 = r0 + 8;
        const bool needmask = (kt * 64 + 63) > (qbase + wrow);
        #pragma unroll
        for (int ni = 0; ni < 8; ni++) {
            #pragma unroll
            for (int f = 0; f < 4; f++) s[ni][f] *= SC2;
            if (needmask) {
                const int col = kt * 64 + ni * 8 + t4 * 2;
                if (col > r0)     s[ni][0] = -1e30f;
                if (col + 1 > r0) s[ni][1] = -1e30f;
                if (col > r1)     s[ni][2] = -1e30f;
                if (col + 1 > r1) s[ni][3] = -1e30f;
            }
        }

        float rm0 = -INFINITY, rm1 = -INFINITY;
        #pragma unroll
        for (int ni = 0; ni < 8; ni++) {
            rm0 = fmaxf(rm0, fmaxf(s[ni][0], s[ni][1]));
            rm1 = fmaxf(rm1, fmaxf(s[ni][2], s[ni][3]));
        }
        rm0 = fmaxf(rm0, __shfl_xor_sync(0xffffffff, rm0, 1));
        rm0 = fmaxf(rm0, __shfl_xor_sync(0xffffffff, rm0, 2));
        rm1 = fmaxf(rm1, __shfl_xor_sync(0xffffffff, rm1, 1));
        rm1 = fmaxf(rm1, __shfl_xor_sync(0xffffffff, rm1, 2));

        const float nm0 = fmaxf(m0, rm0), nm1 = fmaxf(m1, rm1);
        const float al0 = exp2f(m0 - nm0), al1 = exp2f(m1 - nm1);
        l0 *= al0; l1 *= al1;
        m0 = nm0; m1 = nm1;
        #pragma unroll
        for (int ni = 0; ni < 8; ni++) {
            o[ni][0] *= al0; o[ni][1] *= al0;
            o[ni][2] *= al1; o[ni][3] *= al1;
        }

        uint32_t pf[8][2];
        float la0 = 0.f, la1 = 0.f;
        #pragma unroll
        for (int ni = 0; ni < 8; ni++) {
            __half2 t0 = __floats2half2_rn(fmaxf(s[ni][0] - m0, -60.f),
                                           fmaxf(s[ni][1] - m0, -60.f));
            __half2 t1 = __floats2half2_rn(fmaxf(s[ni][2] - m1, -60.f),
                                           fmaxf(s[ni][3] - m1, -60.f));
            uint32_t p0 = h2ex2(*(uint32_t*)&t0);
            uint32_t p1 = h2ex2(*(uint32_t*)&t1);
            pf[ni][0] = p0; pf[ni][1] = p1;
            float2 f0 = __half22float2(*(__half2*)&p0);
            float2 f1 = __half22float2(*(__half2*)&p1);
            la0 += f0.x + f0.y;
            la1 += f1.x + f1.y;
        }
        la0 += __shfl_xor_sync(0xffffffff, la0, 1);
        la0 += __shfl_xor_sync(0xffffffff, la0, 2);
        la1 += __shfl_xor_sync(0xffffffff, la1, 1);
        la1 += __shfl_xor_sync(0xffffffff, la1, 2);
        l0 += la0; l1 += la1;

        #pragma unroll
        for (int kc = 0; kc < 4; kc++) {
            uint32_t a[4] = { pf[2*kc][0], pf[2*kc][1], pf[2*kc+1][0], pf[2*kc+1][1] };
            #pragma unroll
            for (int ntp = 0; ntp < 4; ntp++) {
                uint32_t rh[4];
                const int off = (kc * 16 + v_row) * ATS + ntp * 16 + v_col;
                ldsm4t(rh, pVh + off);
                mma16816(o[2*ntp+0], a, rh[0], rh[1]);
                mma16816(o[2*ntp+1], a, rh[2], rh[3]);
            }
        }
    }

    const float il0 = 1.0f / l0, il1 = 1.0f / l1;
    const size_t gr0 = (tokb + qbase + wrow + group) * DD + hoff;
    const size_t gr1 = gr0 + 8 * DD;
    #pragma unroll
    for (int ni = 0; ni < 8; ni++) {
        const int col = ni * 8 + t4 * 2;
        *(__half2*)(Ohi + gr0 + col) = __floats2half2_rn(o[ni][0] * il0, o[ni][1] * il0);
        *(__half2*)(Ohi + gr1 + col) = __floats2half2_rn(o[ni][2] * il1, o[ni][3] * il1);
    }
}

// ---------------------------------------------------------------------------
// kernel_launch
// ---------------------------------------------------------------------------
extern "C" void kernel_launch(void* const* d_in, const int* in_sizes, int n_in,
                              void* d_out, int out_size)
{
    const float* x     = (const float*)d_in[0];
    const float* ln1_g = (const float*)d_in[2];
    const float* ln1_b = (const float*)d_in[3];
    const float* ln2_g = (const float*)d_in[4];
    const float* ln2_b = (const float*)d_in[5];
    const float* Wq    = (const float*)d_in[6];
    const float* Wk    = (const float*)d_in[7];
    const float* Wv    = (const float*)d_in[8];
    const float* Wo    = (const float*)d_in[9];
    const float* Wff1  = (const float*)d_in[10];
    const float* Wff2  = (const float*)d_in[11];
    float* out = (float*)d_out;

    unsigned char* base = nullptr;
    cudaGetSymbolAddress((void**)&base, g_scratch);
    size_t off = 0;
    auto carve = [&](size_t bytes) { void* p = base + off; off += bytes; return p; };

    __half* qkv_hi = (__half*)carve((size_t)3 * SEG * 2);   // q | k | v (hi)
    __half* qk_lo  = (__half*)carve((size_t)2 * SEG * 2);   // q | k (lo)
    __half* h_hi   = (__half*)carve((size_t)SEG * 2);
    __half* h_lo   = (__half*)carve((size_t)SEG * 2);
    __half* att_hi = (__half*)carve((size_t)SEG * 2);
    __half* ff_hi  = (__half*)carve((size_t)ROWS * FFD * 2);
    __half* Wqkv_h = (__half*)carve((size_t)3 * DD * DD * 2);   // Wq|Wk|Wv
    __half* Wo_h   = (__half*)carve((size_t)DD * DD * 2);       // after (w2h_attn dst)
    __half* Wff_h  = (__half*)carve((size_t)2 * FFD * DD * 2);

    __half* Wf1_h = Wff_h;
    __half* Wf2_h = Wff_h + (size_t)FFD * DD;
    __half* Wv_h  = Wqkv_h + (size_t)2 * DD * DD;

    const uint32_t SM2 = 2u * 3u * TILE_B;   // NLIMB=2: 2 stages x 48KB = 98304 B
    const uint32_t SM1 = 2u * 2u * TILE_B;   // NLIMB=1: 2 stages x 32KB = 65536 B
    cudaFuncSetAttribute((const void*)gemm_f16<5,2>, cudaFuncAttributeMaxDynamicSharedMemorySize, (int)SM2);
    cudaFuncSetAttribute((const void*)gemm_f16<1,1>, cudaFuncAttributeMaxDynamicSharedMemorySize, (int)SM1);
    cudaFuncSetAttribute((const void*)gemm_f16<2,1>, cudaFuncAttributeMaxDynamicSharedMemorySize, (int)SM1);
    cudaFuncSetAttribute((const void*)gemm_f16<3,1>, cudaFuncAttributeMaxDynamicSharedMemorySize, (int)SM1);
    cudaFuncSetAttribute((const void*)gemm_f16<4,1>, cudaFuncAttributeMaxDynamicSharedMemorySize, (int)SM1);
    cudaFuncSetAttribute((const void*)attn_tc, cudaFuncAttributeMaxDynamicSharedMemorySize, (int)ASMEM);

    w2h_attn<<<4 * DD * DD / 1024, 256>>>(Wq, Wk, Wv, Wo, Wqkv_h);
    w2h_ff<<<2 * FFD * DD / 1024, 256>>>(Wff1, Wff2, Wff_h);

    ln_split_kernel<true><<<ROWS, 256>>>(x, ln1_g, ln1_b, h_hi, h_lo);

    // QK fused: N = 2048, 2-limb, split store (hi+lo)
    gemm_f16<5,2><<<dim3(2 * DD / GN, ROWS / GM), 256, SM2>>>(
        h_hi, h_lo, Wqkv_h, nullptr, nullptr, qkv_hi, qk_lo, ROWS, 2 * DD, DD);

    // V: N = 1024, 1-limb, hi-only store
    gemm_f16<4,1><<<dim3(DD / GN, ROWS / GM), 256, SM1>>>(
        h_hi, nullptr, Wv_h, nullptr, nullptr, qkv_hi + 2 * SEG, nullptr, ROWS, DD, DD);

    // attention: 64 queries / CTA, 4 warps
    attn_tc<<<dim3(TT / AQ, BB * HH), 128, ASMEM>>>(
        qkv_hi, qk_lo, qkv_hi + SEG, qk_lo + SEG, qkv_hi + 2 * SEG, att_hi);

    gemm_f16<1,1><<<dim3(DD / GN, ROWS / GM), 256, SM1>>>(
        att_hi, nullptr, Wo_h, out, x, nullptr, nullptr, ROWS, DD, DD);

    ln_split_kernel<false><<<ROWS, 256>>>(out, ln2_g, ln2_b, h_hi, nullptr);

    gemm_f16<2,1><<<dim3(FFD / GN, ROWS / GM), 256, SM1>>>(
        h_hi, nullptr, Wf1_h, nullptr, nullptr, ff_hi, nullptr, ROWS, FFD, DD);

    gemm_f16<3,1><<<dim3(DD / GN, ROWS / GM), 256, SM1>>>(
        ff_hi, nullptr, Wf2_h, out, nullptr, nullptr, nullptr, ROWS, DD, FFD);
}

// round 14
// speedup vs baseline: 1.1397x; 1.0159x over previous
#include <cuda_runtime.h>
#include <cuda_fp16.h>
#include <math.h>
#include <stdint.h>

// Problem constants
#define BB   2
#define TT   2048
#define DD   1024
#define HH   16
#define DHH  64
#define FFD  4096
#define ROWS (BB*TT)          // 4096
#define SEG  (ROWS * DD)      // 4194304 elements
#define EPSF 1e-5f

__device__ __align__(256) unsigned char g_scratch[190u * 1024u * 1024u];

// ---------------------------------------------------------------------------
// helpers
// ---------------------------------------------------------------------------
__device__ __forceinline__ uint32_t smem_u32(const void* p) {
    uint32_t a;
    asm("{ .reg .u64 t; cvta.to.shared.u64 t, %1; cvt.u32.u64 %0, t; }" : "=r"(a) : "l"(p));
    return a;
}
__device__ __forceinline__ uint32_t sw128(uint32_t bo) {
    return bo ^ ((bo >> 3) & 0x70);
}
__device__ __forceinline__ void cp_async16(uint32_t smem_dst, const void* gmem_src) {
    asm volatile("cp.async.cg.shared.global [%0], [%1], 16;\n" :: "r"(smem_dst), "l"(gmem_src));
}
__device__ __forceinline__ void cp_async16p(void* smem_dst, const void* gmem_src) {
    uint32_t s = smem_u32(smem_dst);
    asm volatile("cp.async.cg.shared.global [%0], [%1], 16;\n" :: "r"(s), "l"(gmem_src));
}
__device__ __forceinline__ void ldsm4a(uint32_t* r, uint32_t a) {
    asm volatile("ldmatrix.sync.aligned.m8n8.x4.shared.b16 {%0,%1,%2,%3}, [%4];"
        : "=r"(r[0]), "=r"(r[1]), "=r"(r[2]), "=r"(r[3]) : "r"(a));
}
__device__ __forceinline__ void ldsm4(uint32_t* r, const __half* p) {
    ldsm4a(r, smem_u32(p));
}
__device__ __forceinline__ void ldsm4t(uint32_t* r, const __half* p) {
    uint32_t a = smem_u32(p);
    asm volatile("ldmatrix.sync.aligned.m8n8.x4.trans.shared.b16 {%0,%1,%2,%3}, [%4];"
        : "=r"(r[0]), "=r"(r[1]), "=r"(r[2]), "=r"(r[3]) : "r"(a));
}
__device__ __forceinline__ void mma16816(float* c, const uint32_t* a, uint32_t b0, uint32_t b1) {
    asm volatile(
        "mma.sync.aligned.m16n8k16.row.col.f32.f16.f16.f32 "
        "{%0,%1,%2,%3}, {%4,%5,%6,%7}, {%8,%9}, {%0,%1,%2,%3};"
        : "+f"(c[0]), "+f"(c[1]), "+f"(c[2]), "+f"(c[3])
        : "r"(a[0]), "r"(a[1]), "r"(a[2]), "r"(a[3]), "r"(b0), "r"(b1));
}
__device__ __forceinline__ uint32_t h2ex2(uint32_t a) {
    uint32_t d;
    asm("ex2.approx.f16x2 %0, %1;" : "=r"(d) : "r"(a));
    return d;
}

// ---------------------------------------------------------------------------
// weight conversion
// ---------------------------------------------------------------------------
__global__ __launch_bounds__(256) void w2h_attn(
    const float* __restrict__ s0, const float* __restrict__ s1,
    const float* __restrict__ s2, const float* __restrict__ s3,
    __half* __restrict__ dst)
{
    const size_t idx = ((size_t)blockIdx.x * 256 + threadIdx.x) * 4;
    const int seg = (int)(idx >> 20);
    const float* s = (seg == 0) ? s0 : (seg == 1) ? s1 : (seg == 2) ? s2 : s3;
    float4 v = *(const float4*)(s + (idx & 0xFFFFF));
    *(__half2*)(dst + idx)     = __floats2half2_rn(v.x, v.y);
    *(__half2*)(dst + idx + 2) = __floats2half2_rn(v.z, v.w);
}
__global__ __launch_bounds__(256) void w2h_ff(
    const float* __restrict__ s0, const float* __restrict__ s1,
    __half* __restrict__ dst)
{
    const size_t idx = ((size_t)blockIdx.x * 256 + threadIdx.x) * 4;
    const int seg = (int)(idx >> 22);
    const float* s = (seg == 0) ? s0 : s1;
    float4 v = *(const float4*)(s + (idx & 0x3FFFFF));
    *(__half2*)(dst + idx)     = __floats2half2_rn(v.x, v.y);
    *(__half2*)(dst + idx + 2) = __floats2half2_rn(v.z, v.w);
}

// ---------------------------------------------------------------------------
// LayerNorm -> fp16 (hi always, lo optional)
// ---------------------------------------------------------------------------
template<bool WRITE_LO>
__global__ __launch_bounds__(256) void ln_split_kernel(
    const float* __restrict__ x, const float* __restrict__ g,
    const float* __restrict__ b, __half* __restrict__ ohi, __half* __restrict__ olo)
{
    const int row = blockIdx.x;
    const int tid = threadIdx.x;
    const float* xr = x + (size_t)row * DD;

    float4 v = *(const float4*)(xr + tid * 4);
    float s  = v.x + v.y + v.z + v.w;
    float ss = v.x * v.x + v.y * v.y + v.z * v.z + v.w * v.w;

    #pragma unroll
    for (int off = 16; off > 0; off >>= 1) {
        s  += __shfl_xor_sync(0xffffffff, s,  off);
        ss += __shfl_xor_sync(0xffffffff, ss, off);
    }
    __shared__ float sbuf[8], ssbuf[8];
    const int warp = tid >> 5, lane = tid & 31;
    if (lane == 0) { sbuf[warp] = s; ssbuf[warp] = ss; }
    __syncthreads();
    float S = 0.f, SS = 0.f;
    #pragma unroll
    for (int i = 0; i < 8; i++) { S += sbuf[i]; SS += ssbuf[i]; }

    const float mu  = S * (1.0f / DD);
    const float var = SS * (1.0f / DD) - mu * mu;
    const float rs  = rsqrtf(var + EPSF);

    float4 gg = *(const float4*)(g + tid * 4);
    float4 bb = *(const float4*)(b + tid * 4);
    float y0 = (v.x - mu) * rs * gg.x + bb.x;
    float y1 = (v.y - mu) * rs * gg.y + bb.y;
    float y2 = (v.z - mu) * rs * gg.z + bb.z;
    float y3 = (v.w - mu) * rs * gg.w + bb.w;

    __half h0 = __float2half_rn(y0), h1 = __float2half_rn(y1);
    __half h2 = __float2half_rn(y2), h3 = __float2half_rn(y3);
    const size_t base = (size_t)row * DD + tid * 4;
    *(__half2*)(ohi + base)     = __halves2half2(h0, h1);
    *(__half2*)(ohi + base + 2) = __halves2half2(h2, h3);
    if (WRITE_LO) {
        *(__half2*)(olo + base)     = __halves2half2(
            __float2half_rn(y0 - __half2float(h0)), __float2half_rn(y1 - __half2float(h1)));
        *(__half2*)(olo + base + 2) = __halves2half2(
            __float2half_rn(y2 - __half2float(h2)), __float2half_rn(y3 - __half2float(h3)));
    }
}

// ---------------------------------------------------------------------------
// fp16 GEMM: C[M,N] = A[M,K] @ W[N,K]^T, A = Ah (+ Al if NLIMB==2)
// 128x128 tile, BK=64 (128B rows, XOR-swizzled), 2-stage cp.async,
// ONE __syncthreads per k64 iter. 8 warps (2x4), 64x32 per warp.
// EPI: 1 C=acc+R(f32), 2 gelu->Ohi, 3 C+=acc, 4 hi-store,
//      5 segmented split (Q|K fused: col>>10 picks segment, hi+lo)
// ---------------------------------------------------------------------------
#define GM 128
#define GN 128
#define GK 64
#define TILE_B 16384u

template<int EPI, int NLIMB>
__global__ __launch_bounds__(256) void gemm_f16(
    const __half* __restrict__ Ah, const __half* __restrict__ Al,
    const __half* __restrict__ Wh, float* __restrict__ C,
    const float* __restrict__ R, __half* __restrict__ Ohi, __half* __restrict__ Olo,
    int M, int N, int K)
{
    extern __shared__ unsigned char smraw[];
    const uint32_t smb = smem_u32(smraw);

    constexpr int PL = NLIMB + 1;                 // planes per stage (A limbs + W)
    constexpr uint32_t STAGEB = PL * TILE_B;

    const int tid   = threadIdx.x;
    const int lane  = tid & 31;
    const int warp  = tid >> 5;
    const int wm    = (warp >> 2) * 64;
    const int wn    = (warp & 3) * 32;
    const int group = lane >> 2;
    const int t4    = lane & 3;

    const int bm = blockIdx.y * GM;
    const int bn = blockIdx.x * GN;

    const int a_row = (lane & 7) + ((lane >> 3) & 1) * 8;
    const int a_k   = (lane >> 4) * 8;
    const int b_row = (lane & 7) + ((lane >> 4) & 1) * 8;
    const int b_k   = ((lane >> 3) & 1) * 8;

    float c[4][4][4];
    #pragma unroll
    for (int mi = 0; mi < 4; mi++)
        #pragma unroll
        for (int ni = 0; ni < 4; ni++)
            #pragma unroll
            for (int f = 0; f < 4; f++) c[mi][ni][f] = 0.f;

    const int KT = K / GK;

    #define STAGE_LOAD(st, k0)                                                      \
    {                                                                               \
        const uint32_t sb_ = smb + (st) * STAGEB;                                   \
        _Pragma("unroll")                                                           \
        for (int i = 0; i < 4 * PL; i++) {                                          \
            const int pl  = i >> 2;                                                 \
            const int id  = (i & 3) * 256 + tid;                                    \
            const int row = id >> 3;                                                \
            const int kq  = id & 7;                                                 \
            const uint32_t bo = row * 128 + kq * 16;                                \
            const __half* src; size_t gr;                                           \
            if (pl == NLIMB)      { src = Wh; gr = (size_t)(bn + row) * K; }        \
            else if (pl == 0)     { src = Ah; gr = (size_t)(bm + row) * K; }        \
            else                  { src = Al; gr = (size_t)(bm + row) * K; }        \
            cp_async16(sb_ + pl * TILE_B + sw128(bo), src + gr + (k0) + kq * 8);    \
        }                                                                           \
        asm volatile("cp.async.commit_group;\n");                                   \
    }

    STAGE_LOAD(0, 0)

    for (int kt = 0; kt < KT; kt++) {
        asm volatile("cp.async.wait_group 0;\n");
        __syncthreads();                       // data visible + prev stage free
        if (kt + 1 < KT) STAGE_LOAD((kt + 1) & 1, (kt + 1) * GK)

        const uint32_t sb = smb + (kt & 1) * STAGEB;
        #pragma unroll
        for (int ks = 0; ks < 4; ks++) {
            uint32_t bf[4][2];
            #pragma unroll
            for (int ng = 0; ng < 2; ng++) {
                uint32_t r[4];
                ldsm4a(r, sb + NLIMB * TILE_B +
                       sw128((wn + ng * 16 + b_row) * 128 + (ks * 16 + b_k) * 2));
                bf[2 * ng + 0][0] = r[0]; bf[2 * ng + 0][1] = r[1];
                bf[2 * ng + 1][0] = r[2]; bf[2 * ng + 1][1] = r[3];
            }
            #pragma unroll
            for (int mi = 0; mi < 4; mi++) {
                uint32_t ah[4];
                const uint32_t bo = (wm + mi * 16 + a_row) * 128 + (ks * 16 + a_k) * 2;
                ldsm4a(ah, sb + sw128(bo));
                if (NLIMB == 2) {
                    uint32_t al[4];
                    ldsm4a(al, sb + TILE_B + sw128(bo));
                    #pragma unroll
                    for (int ni = 0; ni < 4; ni++) {
                        mma16816(c[mi][ni], ah, bf[ni][0], bf[ni][1]);
                        mma16816(c[mi][ni], al, bf[ni][0], bf[ni][1]);
                    }
                } else {
                    #pragma unroll
                    for (int ni = 0; ni < 4; ni++)
                        mma16816(c[mi][ni], ah, bf[ni][0], bf[ni][1]);
                }
            }
        }
    }

    // epilogue
    #pragma unroll
    for (int mi = 0; mi < 4; mi++) {
        #pragma unroll
        for (int hf = 0; hf < 2; hf++) {
            const int row = bm + wm + mi * 16 + group + hf * 8;
            #pragma unroll
            for (int ni = 0; ni < 4; ni++) {
                const int col = bn + wn + ni * 8 + t4 * 2;
                float v0 = c[mi][ni][hf * 2 + 0];
                float v1 = c[mi][ni][hf * 2 + 1];
                if (EPI == 1) {
                    float2 rr = *(const float2*)(R + (size_t)row * N + col);
                    float2 o; o.x = v0 + rr.x; o.y = v1 + rr.y;
                    *(float2*)(C + (size_t)row * N + col) = o;
                } else if (EPI == 2) {
                    v0 = 0.5f * v0 * (1.0f + erff(v0 * 0.70710678118654752f));
                    v1 = 0.5f * v1 * (1.0f + erff(v1 * 0.70710678118654752f));
                    *(__half2*)(Ohi + (size_t)row * N + col) =
                        __floats2half2_rn(v0, v1);
                } else if (EPI == 4) {
                    *(__half2*)(Ohi + (size_t)row * N + col) =
                        __floats2half2_rn(v0, v1);
                } else if (EPI == 5) {
                    const int seg = col >> 10;
                    const int lc  = col & 1023;
                    const size_t di = ((size_t)seg * ROWS + row) * DD + lc;
                    __half h0 = __float2half_rn(v0), h1 = __float2half_rn(v1);
                    *(__half2*)(Ohi + di) = __halves2half2(h0, h1);
                    *(__half2*)(Olo + di) = __halves2half2(
                        __float2half_rn(v0 - __half2float(h0)),
                        __float2half_rn(v1 - __half2float(h1)));
                } else {  // EPI == 3
                    float2 cc = *(const float2*)(C + (size_t)row * N + col);
                    float2 o; o.x = v0 + cc.x; o.y = v1 + cc.y;
                    *(float2*)(C + (size_t)row * N + col) = o;
                }
            }
        }
    }
}

// ---------------------------------------------------------------------------
// Tensor-core causal flash attention — 128 threads (4 warps), 64 queries/CTA.
// 64-key tiles (Kh,Kl,Vh) double-buffered; S = QhKh+QlKh+QhKl; P@Vh.
// l accumulated via ones-MMA (P @ 1 = row sums in accumulator).
// ---------------------------------------------------------------------------
#define ATS 72
#define AQ  64                       // queries per CTA
#define QBUF (AQ * ATS)
#define KVT  (64 * ATS)
#define KVSTG3 (3 * KVT)
#define ASMEM ((2u * KVSTG3 + 2u * QBUF) * sizeof(__half))   // 73728 B

__global__ __launch_bounds__(128) void attn_tc(
    const __half* __restrict__ Qh, const __half* __restrict__ Ql,
    const __half* __restrict__ Kh, const __half* __restrict__ Kl,
    const __half* __restrict__ Vh,
    __half* __restrict__ Ohi)
{
    extern __shared__ __half sm[];
    __half* sKV = sm;                  // [2][KVSTG3]
    __half* sQh = sm + 2 * KVSTG3;
    __half* sQl = sQh + QBUF;

    const int tid  = threadIdx.x;
    const int lane = tid & 31;
    const int warp = tid >> 5;         // 0..3
    const int wrow = warp * 16;
    const int group = lane >> 2;
    const int t4    = lane & 3;

    const int qtile = gridDim.x - 1 - blockIdx.x;   // long blocks first
    const int bh = blockIdx.y;
    const int b = bh >> 4, h = bh & 15;
    const int qbase = qtile * AQ;
    const int hoff  = h * DHH;
    const size_t tokb = (size_t)b * TT;

    const int a_row = (lane & 7) + ((lane >> 3) & 1) * 8;
    const int a_k   = (lane >> 4) * 8;
    const int b_row = (lane & 7) + ((lane >> 4) & 1) * 8;
    const int b_k   = ((lane >> 3) & 1) * 8;
    const int v_row = (lane & 7) + ((lane >> 3) & 1) * 8;
    const int v_col = (lane >> 4) * 8;

    // group 0: Q (hi + lo)
    #pragma unroll
    for (int i = 0; i < 8; i++) {
        const int buf = i >> 2;                 // 0 = hi, 1 = lo
        const int within = (i & 3) * 128 + tid; // 0..511
        const int row = within >> 3;
        const int c8  = (within & 7) * 8;
        const __half* src = (buf == 0 ? Qh : Ql) + (tokb + qbase + row) * DD + hoff + c8;
        cp_async16p((buf == 0 ? sQh : sQl) + row * ATS + c8, src);
    }
    asm volatile("cp.async.commit_group;\n");

    #define KV_LOAD(st, key0)                                                        \
    {                                                                                \
        _Pragma("unroll")                                                            \
        for (int i = 0; i < 12; i++) {                                               \
            const int tile = i >> 2;                                                 \
            const int within = (i & 3) * 128 + tid;                                  \
            const int row  = within >> 3;                                            \
            const int c8   = (within & 7) * 8;                                       \
            const __half* src = (tile == 0 ? Kh : tile == 1 ? Kl : Vh)               \
                                + (tokb + (key0) + row) * DD + hoff + c8;            \
            cp_async16p(&sKV[(st) * KVSTG3 + tile * KVT + row * ATS + c8], src);     \
        }                                                                            \
        asm volatile("cp.async.commit_group;\n");                                    \
    }

    KV_LOAD(0, 0)                                // group 1
    asm volatile("cp.async.wait_group 1;\n");    // Q done
    __syncthreads();

    uint32_t qfh[4][4], qfl[4][4];
    #pragma unroll
    for (int kc = 0; kc < 4; kc++) {
        const int off = (wrow + a_row) * ATS + kc * 16 + a_k;
        ldsm4(qfh[kc], &sQh[off]);
        ldsm4(qfl[kc], &sQl[off]);
    }

    float o[8][4];
    #pragma unroll
    for (int ni = 0; ni < 8; ni++)
        #pragma unroll
        for (int f = 0; f < 4; f++) o[ni][f] = 0.f;
    float m0 = -INFINITY, m1 = -INFINITY, l0 = 0.f, l1 = 0.f;

    const float SC2 = 0.125f * 1.4426950408889634f;
    const uint32_t ONES2 = 0x3C003C00u;          // half2(1.0, 1.0)
    const int nkt = qtile + 1;

    for (int kt = 0; kt < nkt; kt++) {
        const int st = kt & 1;
        asm volatile("cp.async.wait_group 0;\n");   // kv(kt) done
        __syncthreads();
        if (kt + 1 < nkt) KV_LOAD(st ^ 1, (kt + 1) * 64)

        const __half* pKh = &sKV[st * KVSTG3 + 0 * KVT];
        const __half* pKl = &sKV[st * KVSTG3 + 1 * KVT];
        const __half* pVh = &sKV[st * KVSTG3 + 2 * KVT];

        float s[8][4];
        #pragma unroll
        for (int ni = 0; ni < 8; ni++)
            #pragma unroll
            for (int f = 0; f < 4; f++) s[ni][f] = 0.f;

        #pragma unroll
        for (int kc = 0; kc < 4; kc++) {
            #pragma unroll
            for (int ntp = 0; ntp < 4; ntp++) {
                uint32_t rh[4], rl[4];
                const int off = (ntp * 16 + b_row) * ATS + kc * 16 + b_k;
                ldsm4(rh, pKh + off);
                ldsm4(rl, pKl + off);
                mma16816(s[2*ntp+0], qfh[kc], rh[0], rh[1]);
                mma16816(s[2*ntp+1], qfh[kc], rh[2], rh[3]);
                mma16816(s[2*ntp+0], qfl[kc], rh[0], rh[1]);
                mma16816(s[2*ntp+1], qfl[kc], rh[2], rh[3]);
                mma16816(s[2*ntp+0], qfh[kc], rl[0], rl[1]);
                mma16816(s[2*ntp+1], qfh[kc], rl[2], rl[3]);
            }
        }

        const int r0 = qbase + wrow + group;
        const int r1 = r0 + 8;
        const bool needmask = (kt * 64 + 63) > (qbase + wrow);
        #pragma unroll
        for (int ni = 0; ni < 8; ni++) {
            #pragma unroll
            for (int f = 0; f < 4; f++) s[ni][f] *= SC2;
            if (needmask) {
                const int col = kt * 64 + ni * 8 + t4 * 2;
                if (col > r0)     s[ni][0] = -1e30f;
                if (col + 1 > r0) s[ni][1] = -1e30f;
                if (col > r1)     s[ni][2] = -1e30f;
                if (col + 1 > r1) s[ni][3] = -1e30f;
            }
        }

        float rm0 = -INFINITY, rm1 = -INFINITY;
        #pragma unroll
        for (int ni = 0; ni < 8; ni++) {
            rm0 = fmaxf(rm0, fmaxf(s[ni][0], s[ni][1]));
            rm1 = fmaxf(rm1, fmaxf(s[ni][2], s[ni][3]));
        }
        rm0 = fmaxf(rm0, __shfl_xor_sync(0xffffffff, rm0, 1));
        rm0 = fmaxf(rm0, __shfl_xor_sync(0xffffffff, rm0, 2));
        rm1 = fmaxf(rm1, __shfl_xor_sync(0xffffffff, rm1, 1));
        rm1 = fmaxf(rm1, __shfl_xor_sync(0xffffffff, rm1, 2));

        const float nm0 = fmaxf(m0, rm0), nm1 = fmaxf(m1, rm1);
        const float al0 = exp2f(m0 - nm0), al1 = exp2f(m1 - nm1);
        l0 *= al0; l1 *= al1;
        m0 = nm0; m1 = nm1;
        #pragma unroll
        for (int ni = 0; ni < 8; ni++) {
            o[ni][0] *= al0; o[ni][1] *= al0;
            o[ni][2] *= al1; o[ni][3] *= al1;
        }

        // p = exp2(s - m) in fp16x2 (masked -> -inf -> 0; m is finite)
        uint32_t pf[8][2];
        #pragma unroll
        for (int ni = 0; ni < 8; ni++) {
            __half2 t0 = __floats2half2_rn(s[ni][0] - m0, s[ni][1] - m0);
            __half2 t1 = __floats2half2_rn(s[ni][2] - m1, s[ni][3] - m1);
            pf[ni][0] = h2ex2(*(uint32_t*)&t0);
            pf[ni][1] = h2ex2(*(uint32_t*)&t1);
        }

        // O += P @ Vh; l += P @ ones (row sums via MMA, no cvt/shuffles)
        float lacc[4] = {0.f, 0.f, 0.f, 0.f};
        #pragma unroll
        for (int kc = 0; kc < 4; kc++) {
            uint32_t a[4] = { pf[2*kc][0], pf[2*kc][1], pf[2*kc+1][0], pf[2*kc+1][1] };
            mma16816(lacc, a, ONES2, ONES2);
            #pragma unroll
            for (int ntp = 0; ntp < 4; ntp++) {
                uint32_t rh[4];
                const int off = (kc * 16 + v_row) * ATS + ntp * 16 + v_col;
                ldsm4t(rh, pVh + off);
                mma16816(o[2*ntp+0], a, rh[0], rh[1]);
                mma16816(o[2*ntp+1], a, rh[2], rh[3]);
            }
        }
        l0 += lacc[0];
        l1 += lacc[2];
    }

    const float il0 = 1.0f / l0, il1 = 1.0f / l1;
    const size_t gr0 = (tokb + qbase + wrow + group) * DD + hoff;
    const size_t gr1 = gr0 + 8 * DD;
    #pragma unroll
    for (int ni = 0; ni < 8; ni++) {
        const int col = ni * 8 + t4 * 2;
        *(__half2*)(Ohi + gr0 + col) = __floats2half2_rn(o[ni][0] * il0, o[ni][1] * il0);
        *(__half2*)(Ohi + gr1 + col) = __floats2half2_rn(o[ni][2] * il1, o[ni][3] * il1);
    }
}

// ---------------------------------------------------------------------------
// kernel_launch
// ---------------------------------------------------------------------------
extern "C" void kernel_launch(void* const* d_in, const int* in_sizes, int n_in,
                              void* d_out, int out_size)
{
    const float* x     = (const float*)d_in[0];
    const float* ln1_g = (const float*)d_in[2];
    const float* ln1_b = (const float*)d_in[3];
    const float* ln2_g = (const float*)d_in[4];
    const float* ln2_b = (const float*)d_in[5];
    const float* Wq    = (const float*)d_in[6];
    const float* Wk    = (const float*)d_in[7];
    const float* Wv    = (const float*)d_in[8];
    const float* Wo    = (const float*)d_in[9];
    const float* Wff1  = (const float*)d_in[10];
    const float* Wff2  = (const float*)d_in[11];
    float* out = (float*)d_out;

    unsigned char* base = nullptr;
    cudaGetSymbolAddress((void**)&base, g_scratch);
    size_t off = 0;
    auto carve = [&](size_t bytes) { void* p = base + off; off += bytes; return p; };

    __half* qkv_hi = (__half*)carve((size_t)3 * SEG * 2);   // q | k | v (hi)
    __half* qk_lo  = (__half*)carve((size_t)2 * SEG * 2);   // q | k (lo)
    __half* h_hi   = (__half*)carve((size_t)SEG * 2);
    __half* h_lo   = (__half*)carve((size_t)SEG * 2);
    __half* att_hi = (__half*)carve((size_t)SEG * 2);
    __half* ff_hi  = (__half*)carve((size_t)ROWS * FFD * 2);
    __half* Wqkv_h = (__half*)carve((size_t)3 * DD * DD * 2);   // Wq|Wk|Wv
    __half* Wo_h   = (__half*)carve((size_t)DD * DD * 2);       // after (w2h_attn dst)
    __half* Wff_h  = (__half*)carve((size_t)2 * FFD * DD * 2);

    __half* Wf1_h = Wff_h;
    __half* Wf2_h = Wff_h + (size_t)FFD * DD;
    __half* Wv_h  = Wqkv_h + (size_t)2 * DD * DD;

    const uint32_t SM2 = 2u * 3u * TILE_B;   // NLIMB=2: 2 stages x 48KB = 98304 B
    const uint32_t SM1 = 2u * 2u * TILE_B;   // NLIMB=1: 2 stages x 32KB = 65536 B
    cudaFuncSetAttribute((const void*)gemm_f16<5,2>, cudaFuncAttributeMaxDynamicSharedMemorySize, (int)SM2);
    cudaFuncSetAttribute((const void*)gemm_f16<1,1>, cudaFuncAttributeMaxDynamicSharedMemorySize, (int)SM1);
    cudaFuncSetAttribute((const void*)gemm_f16<2,1>, cudaFuncAttributeMaxDynamicSharedMemorySize, (int)SM1);
    cudaFuncSetAttribute((const void*)gemm_f16<3,1>, cudaFuncAttributeMaxDynamicSharedMemorySize, (int)SM1);
    cudaFuncSetAttribute((const void*)gemm_f16<4,1>, cudaFuncAttributeMaxDynamicSharedMemorySize, (int)SM1);
    cudaFuncSetAttribute((const void*)attn_tc, cudaFuncAttributeMaxDynamicSharedMemorySize, (int)ASMEM);

    w2h_attn<<<4 * DD * DD / 1024, 256>>>(Wq, Wk, Wv, Wo, Wqkv_h);
    w2h_ff<<<2 * FFD * DD / 1024, 256>>>(Wff1, Wff2, Wff_h);

    ln_split_kernel<true><<<ROWS, 256>>>(x, ln1_g, ln1_b, h_hi, h_lo);

    // QK fused: N = 2048, 2-limb, split store (hi+lo)
    gemm_f16<5,2><<<dim3(2 * DD / GN, ROWS / GM), 256, SM2>>>(
        h_hi, h_lo, Wqkv_h, nullptr, nullptr, qkv_hi, qk_lo, ROWS, 2 * DD, DD);

    // V: N = 1024, 1-limb, hi-only store
    gemm_f16<4,1><<<dim3(DD / GN, ROWS / GM), 256, SM1>>>(
        h_hi, nullptr, Wv_h, nullptr, nullptr, qkv_hi + 2 * SEG, nullptr, ROWS, DD, DD);

    // attention: 64 queries / CTA, 4 warps
    attn_tc<<<dim3(TT / AQ, BB * HH), 128, ASMEM>>>(
        qkv_hi, qk_lo, qkv_hi + SEG, qk_lo + SEG, qkv_hi + 2 * SEG, att_hi);

    gemm_f16<1,1><<<dim3(DD / GN, ROWS / GM), 256, SM1>>>(
        att_hi, nullptr, Wo_h, out, x, nullptr, nullptr, ROWS, DD, DD);

    ln_split_kernel<false><<<ROWS, 256>>>(out, ln2_g, ln2_b, h_hi, nullptr);

    gemm_f16<2,1><<<dim3(FFD / GN, ROWS / GM), 256, SM1>>>(
        h_hi, nullptr, Wf1_h, nullptr, nullptr, ff_hi, nullptr, ROWS, FFD, DD);

    gemm_f16<3,1><<<dim3(DD / GN, ROWS / GM), 256, SM1>>>(
        ff_hi, nullptr, Wf2_h, out, nullptr, nullptr, nullptr, ROWS, DD, FFD);
}